// round 1
// baseline (speedup 1.0000x reference)
#include <cuda_runtime.h>
#include <math.h>

#define Bc 128
#define Sc 64
#define FIN 32
#define Ec 96
#define E2c 192
#define Hc 8
#define Dc 24
#define Lc 4
#define HORc 24
#define FLATc (Sc*E2c)          // 12288
#define ROWS (Bc*Sc)            // 8192
#define MLPH (4*Ec)             // 384

// ---------------- scratch (static device globals; no allocation) ----------
__device__ float g_h0[ROWS*Ec];        // after proj stage (B,S,96)
__device__ float g_conv[ROWS*E2c];     // conv output pre-LN
__device__ float g_h[ROWS*E2c];        // main hidden (B,S,192) == (B, FLAT)
__device__ float g_qk[ROWS*E2c];
__device__ float g_v[ROWS*E2c];
__device__ float g_mass[Bc*Hc*Sc];     // (b,h,s)
__device__ float g_att[ROWS*E2c];
__device__ float g_mlp[ROWS*MLPH];
__device__ float g_f[Bc*FLATc];

// ---------------- helpers -------------------------------------------------
__device__ __forceinline__ float gelu_f(float x) {
  // jax.nn.gelu default: tanh approximation
  float t = tanhf(0.7978845608028654f * (x + 0.044715f * x * x * x));
  return 0.5f * x * (1.f + t);
}
__device__ __forceinline__ float softplus_f(float x) {
  return fmaxf(x, 0.f) + log1pf(expf(-fabsf(x)));
}
// block reduce of (a,b); valid for blockDim <= 256
__device__ __forceinline__ void blk_reduce2(float& a, float& b) {
  __shared__ float ra[256], rb[256];
  int t = threadIdx.x, n = blockDim.x;
  ra[t] = a; rb[t] = b;
  __syncthreads();
  #pragma unroll
  for (int s = 128; s > 0; s >>= 1) {
    if (t < s && t + s < n) { ra[t] += ra[t+s]; rb[t] += rb[t+s]; }
    __syncthreads();
  }
  a = ra[0]; b = rb[0];
}

// ---------------- stage 1: proj -> LN -> gelu -----------------------------
// grid ROWS, block Ec(=96). One thread per output feature.
__global__ void k_proj(const float* __restrict__ x, const float* __restrict__ w,
                       const float* __restrict__ bias, const float* __restrict__ ls,
                       const float* __restrict__ lo) {
  int row = blockIdx.x;
  int e = threadIdx.x;
  __shared__ float xs[FIN];
  if (e < FIN) xs[e] = x[row*FIN + e];
  __syncthreads();
  float acc = bias[e];
  #pragma unroll
  for (int k = 0; k < FIN; k++) acc = fmaf(xs[k], w[k*Ec + e], acc);
  float s1 = acc, s2 = acc*acc;
  blk_reduce2(s1, s2);
  float mu = s1 * (1.f/Ec);
  float var = s2 * (1.f/Ec) - mu*mu;
  float y = (acc - mu) * rsqrtf(var + 1e-5f) * ls[e] + lo[e];
  g_h0[row*Ec + e] = gelu_f(y);
}

// ---------------- stage 2: 4x4 SAME conv (image = 128x64x96 -> 192) -------
// SAME even-kernel padding: input idx = i - 1 + di, di in [0,4)
// grid (4 jtiles, 128 rows), block 192 (one thread per output channel)
__global__ void k_conv(const float* __restrict__ cw) {
  int i  = blockIdx.y;
  int j0 = blockIdx.x * 16;
  int oc = threadIdx.x;                 // 0..191
  __shared__ float sp[4][19*Ec];        // rows i-1..i+2, cols j0-1..j0+17
  for (int idx = oc; idx < 4*19*Ec; idx += E2c) {
    int di  = idx / (19*Ec);
    int rem = idx - di*19*Ec;
    int col = rem / Ec;
    int c   = rem - col*Ec;
    int gi = i - 1 + di;
    int gj = j0 - 1 + col;
    float v = 0.f;
    if (gi >= 0 && gi < Bc && gj >= 0 && gj < Sc)
      v = g_h0[(gi*Sc + gj)*Ec + c];
    sp[di][col*Ec + c] = v;
  }
  __syncthreads();
  float acc[16];
  #pragma unroll
  for (int j = 0; j < 16; j++) acc[j] = 0.f;
  for (int di = 0; di < 4; di++) {
    for (int c = 0; c < Ec; c++) {
      float pv[19];
      #pragma unroll
      for (int t = 0; t < 19; t++) pv[t] = sp[di][t*Ec + c];   // broadcast
      #pragma unroll
      for (int dj = 0; dj < 4; dj++) {
        float wv = cw[((di*4 + dj)*Ec + c)*E2c + oc];          // coalesced
        #pragma unroll
        for (int j = 0; j < 16; j++) acc[j] = fmaf(pv[j + dj], wv, acc[j]);
      }
    }
  }
  #pragma unroll
  for (int j = 0; j < 16; j++)
    g_conv[(i*Sc + j0 + j)*E2c + oc] = acc[j];
}

// ---------------- stage 3: conv bias -> LN -> gelu ------------------------
__global__ void k_ln_gelu_conv(const float* __restrict__ cb,
                               const float* __restrict__ ls, const float* __restrict__ lo) {
  int row = blockIdx.x; int e = threadIdx.x;   // 192
  float v = g_conv[row*E2c + e] + cb[e];
  float s1 = v, s2 = v*v;
  blk_reduce2(s1, s2);
  float mu = s1 * (1.f/E2c);
  float var = s2 * (1.f/E2c) - mu*mu;
  g_h[row*E2c + e] = gelu_f((v - mu) * rsqrtf(var + 1e-5f) * ls[e] + lo[e]);
}

// ---------------- generic fp32 GEMM: C = act(A@W + bias) (+ res) ----------
// BM=64, BN=64, BK=16, 256 threads, 4x4 microtile. All dims divisible.
#define BM 64
#define BN 64
#define BK 16
__global__ void k_gemm(const float* __restrict__ A, const float* __restrict__ W,
                       const float* __restrict__ bias, const float* res,
                       float* C, int M, int N, int K, int act) {
  __shared__ float As[BK][BM+1];
  __shared__ float Bs[BK][BN];
  int bn = blockIdx.x * BN, bm = blockIdx.y * BM;
  int tid = threadIdx.x;
  int tx = tid & 15, ty = tid >> 4;
  float acc[4][4];
  #pragma unroll
  for (int i = 0; i < 4; i++)
    #pragma unroll
    for (int j = 0; j < 4; j++) acc[i][j] = 0.f;
  for (int k0 = 0; k0 < K; k0 += BK) {
    #pragma unroll
    for (int i = 0; i < 4; i++) {
      int idx = tid + i*256;
      int m = idx >> 4, kk = idx & 15;
      As[kk][m] = A[(bm + m)*K + k0 + kk];
    }
    #pragma unroll
    for (int i = 0; i < 4; i++) {
      int idx = tid + i*256;
      int kk = idx >> 6, n = idx & 63;
      Bs[kk][n] = W[(k0 + kk)*N + bn + n];
    }
    __syncthreads();
    #pragma unroll
    for (int kk = 0; kk < BK; kk++) {
      float a[4], bb[4];
      #pragma unroll
      for (int i = 0; i < 4; i++) a[i] = As[kk][ty*4 + i];
      #pragma unroll
      for (int j = 0; j < 4; j++) bb[j] = Bs[kk][tx*4 + j];
      #pragma unroll
      for (int i = 0; i < 4; i++)
        #pragma unroll
        for (int j = 0; j < 4; j++) acc[i][j] = fmaf(a[i], bb[j], acc[i][j]);
    }
    __syncthreads();
  }
  #pragma unroll
  for (int i = 0; i < 4; i++) {
    int m = bm + ty*4 + i;
    #pragma unroll
    for (int j = 0; j < 4; j++) {
      int n = bn + tx*4 + j;
      float c = acc[i][j] + bias[n];
      if (act == 1) c = gelu_f(c);
      if (res) c += res[(size_t)m*N + n];
      C[(size_t)m*N + n] = c;
    }
  }
}

// ---------------- mass head: softplus(h @ mass_w + b), stored (b,h,s) -----
// grid ROWS/32, block 256 (32 rows x 8 heads)
__global__ void k_mass(const float* __restrict__ mw, const float* __restrict__ mb) {
  __shared__ float hs[32][E2c+1];
  __shared__ float ws[E2c*Hc];
  int r0 = blockIdx.x * 32;
  int tid = threadIdx.x;
  for (int idx = tid; idx < 32*E2c; idx += 256) {
    int r = idx / E2c, k = idx - (idx / E2c)*E2c;
    hs[r][k] = g_h[(r0 + r)*E2c + k];
  }
  for (int idx = tid; idx < E2c*Hc; idx += 256) ws[idx] = mw[idx];
  __syncthreads();
  int r = tid >> 3, hh = tid & 7;
  float acc = mb[hh];
  #pragma unroll 4
  for (int k = 0; k < E2c; k++) acc = fmaf(hs[r][k], ws[k*Hc + hh], acc);
  int row = r0 + r; int b = row >> 6, s = row & 63;
  g_mass[(b*Hc + hh)*Sc + s] = softplus_f(acc);
}

// ---------------- gravity attention core ----------------------------------
// one block per (b,h): S x S scores, online softmax, out = w @ v
__global__ void k_attn() {
  int bh = blockIdx.x; int b = bh >> 3, hh = bh & 7;
  int i = threadIdx.x;                  // 0..63
  __shared__ float qs[Sc][Dc+1];
  __shared__ float vs[Sc][Dc+1];
  __shared__ float ms[Sc];
  __shared__ float sq[Sc];
  const float* qbase = g_qk + (size_t)(b*Sc)*E2c + hh*Dc;
  const float* vbase = g_v  + (size_t)(b*Sc)*E2c + hh*Dc;
  float qi[Dc];
  float ssq = 0.f;
  #pragma unroll
  for (int d = 0; d < Dc; d++) {
    float q = qbase[i*E2c + d];
    qs[i][d] = q; qi[d] = q; ssq = fmaf(q, q, ssq);
    vs[i][d] = vbase[i*E2c + d];
  }
  sq[i] = ssq;
  ms[i] = g_mass[(b*Hc + hh)*Sc + i];
  __syncthreads();
  float mi = ms[i];
  float mmax = -INFINITY, l = 0.f;
  float acc[Dc];
  #pragma unroll
  for (int d = 0; d < Dc; d++) acc[d] = 0.f;
  for (int j = 0; j < Sc; j++) {
    float dot = 0.f;
    #pragma unroll
    for (int d = 0; d < Dc; d++) dot = fmaf(qi[d], qs[j][d], dot);
    float d2 = fmaxf(ssq + sq[j] - 2.f*dot, 0.f) + 1e-6f;
    float sc = mi * ms[j] / d2;
    float mn = fmaxf(mmax, sc);
    float scale = __expf(mmax - mn);    // first iter: exp(-inf)=0
    float p = __expf(sc - mn);
    l = l*scale + p;
    #pragma unroll
    for (int d = 0; d < Dc; d++) acc[d] = fmaf(p, vs[j][d], acc[d]*scale);
    mmax = mn;
  }
  float inv = 1.f / l;
  float* obase = g_att + (size_t)(b*Sc + i)*E2c + hh*Dc;
  #pragma unroll
  for (int d = 0; d < Dc; d++) obase[d] = acc[d] * inv;
}

// ---------------- residual + LN + gelu ------------------------------------
__global__ void k_res_ln_gelu(const float* __restrict__ ls, const float* __restrict__ lo) {
  int row = blockIdx.x; int e = threadIdx.x;   // 192
  float v = g_h[row*E2c + e] + g_att[row*E2c + e];
  float s1 = v, s2 = v*v;
  blk_reduce2(s1, s2);
  float mu = s1 * (1.f/E2c);
  float var = s2 * (1.f/E2c) - mu*mu;
  g_h[row*E2c + e] = gelu_f((v - mu) * rsqrtf(var + 1e-5f) * ls[e] + lo[e]);
}

// ---------------- LN over FLAT (after fc gelu) ----------------------------
__global__ void k_ln_flat(const float* __restrict__ ls, const float* __restrict__ lo) {
  int b = blockIdx.x; int t = threadIdx.x;     // 256
  float* frow = g_f + (size_t)b*FLATc;
  float s1 = 0.f, s2 = 0.f;
  for (int k = t; k < FLATc; k += 256) { float v = frow[k]; s1 += v; s2 += v*v; }
  blk_reduce2(s1, s2);
  float mu = s1 * (1.f/FLATc);
  float var = s2 * (1.f/FLATc) - mu*mu;
  float rs = rsqrtf(var + 1e-5f);
  for (int k = t; k < FLATc; k += 256) {
    float v = frow[k];
    frow[k] = (v - mu) * rs * ls[k] + lo[k];
  }
}

// ---------------- final out GEMM (128 x 24, K=12288) ----------------------
__global__ void k_out(const float* __restrict__ ow, const float* __restrict__ ob,
                      float* __restrict__ out) {
  int o = blockIdx.x, b = blockIdx.y;
  int t = threadIdx.x;                          // 256
  const float* frow = g_f + (size_t)b*FLATc;
  float s1 = 0.f, s2 = 0.f;
  for (int k = t; k < FLATc; k += 256) s1 = fmaf(frow[k], ow[(size_t)k*HORc + o], s1);
  blk_reduce2(s1, s2);
  if (t == 0) out[b*HORc + o] = s1 + ob[o];
}

// ---------------- launch ---------------------------------------------------
extern "C" void kernel_launch(void* const* d_in, const int* in_sizes, int n_in,
                              void* d_out, int out_size) {
  const float* x      = (const float*)d_in[0];
  const float* proj_w = (const float*)d_in[1];
  const float* proj_b = (const float*)d_in[2];
  const float* ln0_s  = (const float*)d_in[3];
  const float* ln0_o  = (const float*)d_in[4];
  const float* conv_w = (const float*)d_in[5];
  const float* conv_b = (const float*)d_in[6];
  const float* ln1_s  = (const float*)d_in[7];
  const float* ln1_o  = (const float*)d_in[8];
  const float* qk_w   = (const float*)d_in[9];
  const float* qk_b   = (const float*)d_in[10];
  const float* mass_w = (const float*)d_in[11];
  const float* mass_b = (const float*)d_in[12];
  const float* v_w    = (const float*)d_in[13];
  const float* v_b    = (const float*)d_in[14];
  const float* norm_s = (const float*)d_in[15];
  const float* norm_o = (const float*)d_in[16];
  const float* mlp_w1 = (const float*)d_in[17];
  const float* mlp_b1 = (const float*)d_in[18];
  const float* mlp_w2 = (const float*)d_in[19];
  const float* mlp_b2 = (const float*)d_in[20];
  const float* fc_w   = (const float*)d_in[21];
  const float* fc_b   = (const float*)d_in[22];
  const float* ln2_s  = (const float*)d_in[23];
  const float* ln2_o  = (const float*)d_in[24];
  const float* out_w  = (const float*)d_in[25];
  const float* out_b  = (const float*)d_in[26];

  float *p_h, *p_qk, *p_v, *p_mlp, *p_f;
  cudaGetSymbolAddress((void**)&p_h,   g_h);
  cudaGetSymbolAddress((void**)&p_qk,  g_qk);
  cudaGetSymbolAddress((void**)&p_v,   g_v);
  cudaGetSymbolAddress((void**)&p_mlp, g_mlp);
  cudaGetSymbolAddress((void**)&p_f,   g_f);

  k_proj<<<ROWS, Ec>>>(x, proj_w, proj_b, ln0_s, ln0_o);
  k_conv<<<dim3(4, Bc), E2c>>>(conv_w);
  k_ln_gelu_conv<<<ROWS, E2c>>>(conv_b, ln1_s, ln1_o);

  for (int l = 0; l < Lc; l++) {
    k_gemm<<<dim3(E2c/BN, ROWS/BM), 256>>>(p_h, qk_w + (size_t)l*E2c*E2c,
                                           qk_b + l*E2c, nullptr, p_qk,
                                           ROWS, E2c, E2c, 0);
    k_gemm<<<dim3(E2c/BN, ROWS/BM), 256>>>(p_h, v_w + (size_t)l*E2c*E2c,
                                           v_b + l*E2c, nullptr, p_v,
                                           ROWS, E2c, E2c, 0);
    k_mass<<<ROWS/32, 256>>>(mass_w + (size_t)l*E2c*Hc, mass_b + l*Hc);
    k_attn<<<Bc*Hc, Sc>>>();
    k_res_ln_gelu<<<ROWS, E2c>>>(norm_s + l*E2c, norm_o + l*E2c);
  }

  k_gemm<<<dim3(MLPH/BN, ROWS/BM), 256>>>(p_h, mlp_w1, mlp_b1, nullptr, p_mlp,
                                          ROWS, MLPH, E2c, 1);
  k_gemm<<<dim3(E2c/BN, ROWS/BM), 256>>>(p_mlp, mlp_w2, mlp_b2, p_h, p_h,
                                         ROWS, E2c, MLPH, 0);

  k_gemm<<<dim3(FLATc/BN, Bc/BM), 256>>>(p_h, fc_w, fc_b, nullptr, p_f,
                                         Bc, FLATc, FLATc, 1);
  k_ln_flat<<<Bc, 256>>>(ln2_s, ln2_o);
  k_out<<<dim3(HORc, Bc), 256>>>(out_w, out_b, (float*)d_out);
}

// round 3
// speedup vs baseline: 1.3692x; 1.3692x over previous
#include <cuda_runtime.h>
#include <cuda_bf16.h>
#include <math.h>
#include <stdint.h>

#define Bc 128
#define Sc 64
#define FIN 32
#define Ec 96
#define E2c 192
#define Hc 8
#define Dc 24
#define Lc 4
#define HORc 24
#define FLATc (Sc*E2c)          // 12288
#define ROWS (Bc*Sc)            // 8192
#define MLPH (4*Ec)             // 384

// ---------------- scratch (static device globals; no allocation) ----------
__device__ float g_h0[ROWS*Ec];
__device__ float g_conv[ROWS*E2c];
__device__ float g_h[ROWS*E2c];
__device__ float g_qk[ROWS*E2c];
__device__ float g_v[ROWS*E2c];
__device__ float g_mass[Bc*Hc*Sc];
__device__ float g_att[ROWS*E2c];
__device__ float g_mlp[ROWS*MLPH];
__device__ float g_f[Bc*FLATc];
__device__ __nv_bfloat16 g_Ah[Bc*FLATc];   // fc activations hi
__device__ __nv_bfloat16 g_Al[Bc*FLATc];   // fc activations lo

// ---------------- math helpers --------------------------------------------
__device__ __forceinline__ float gelu_f(float x) {
  float t = tanhf(0.7978845608028654f * (x + 0.044715f * x * x * x));
  return 0.5f * x * (1.f + t);
}
__device__ __forceinline__ float softplus_f(float x) {
  return fmaxf(x, 0.f) + log1pf(expf(-fabsf(x)));
}
__device__ __forceinline__ void blk_reduce2(float& a, float& b) {
  __shared__ float ra[256], rb[256];
  int t = threadIdx.x, n = blockDim.x;
  ra[t] = a; rb[t] = b;
  __syncthreads();
  #pragma unroll
  for (int s = 128; s > 0; s >>= 1) {
    if (t < s && t + s < n) { ra[t] += ra[t+s]; rb[t] += rb[t+s]; }
    __syncthreads();
  }
  a = ra[0]; b = rb[0];
}

// ---------------- stage 1: proj -> LN -> gelu -----------------------------
__global__ void k_proj(const float* __restrict__ x, const float* __restrict__ w,
                       const float* __restrict__ bias, const float* __restrict__ ls,
                       const float* __restrict__ lo) {
  int row = blockIdx.x;
  int e = threadIdx.x;
  __shared__ float xs[FIN];
  if (e < FIN) xs[e] = x[row*FIN + e];
  __syncthreads();
  float acc = bias[e];
  #pragma unroll
  for (int k = 0; k < FIN; k++) acc = fmaf(xs[k], w[k*Ec + e], acc);
  float s1 = acc, s2 = acc*acc;
  blk_reduce2(s1, s2);
  float mu = s1 * (1.f/Ec);
  float var = s2 * (1.f/Ec) - mu*mu;
  float y = (acc - mu) * rsqrtf(var + 1e-5f) * ls[e] + lo[e];
  g_h0[row*Ec + e] = gelu_f(y);
}

// ---------------- stage 2: 4x4 SAME conv ----------------------------------
__global__ void k_conv(const float* __restrict__ cw) {
  int i  = blockIdx.y;
  int j0 = blockIdx.x * 16;
  int oc = threadIdx.x;
  __shared__ float sp[4][19*Ec];
  for (int idx = oc; idx < 4*19*Ec; idx += E2c) {
    int di  = idx / (19*Ec);
    int rem = idx - di*19*Ec;
    int col = rem / Ec;
    int c   = rem - col*Ec;
    int gi = i - 1 + di;
    int gj = j0 - 1 + col;
    float v = 0.f;
    if (gi >= 0 && gi < Bc && gj >= 0 && gj < Sc)
      v = g_h0[(gi*Sc + gj)*Ec + c];
    sp[di][col*Ec + c] = v;
  }
  __syncthreads();
  float acc[16];
  #pragma unroll
  for (int j = 0; j < 16; j++) acc[j] = 0.f;
  for (int di = 0; di < 4; di++) {
    for (int c = 0; c < Ec; c++) {
      float pv[19];
      #pragma unroll
      for (int t = 0; t < 19; t++) pv[t] = sp[di][t*Ec + c];
      #pragma unroll
      for (int dj = 0; dj < 4; dj++) {
        float wv = cw[((di*4 + dj)*Ec + c)*E2c + oc];
        #pragma unroll
        for (int j = 0; j < 16; j++) acc[j] = fmaf(pv[j + dj], wv, acc[j]);
      }
    }
  }
  #pragma unroll
  for (int j = 0; j < 16; j++)
    g_conv[(i*Sc + j0 + j)*E2c + oc] = acc[j];
}

// ---------------- stage 3: conv bias -> LN -> gelu ------------------------
__global__ void k_ln_gelu_conv(const float* __restrict__ cb,
                               const float* __restrict__ ls, const float* __restrict__ lo) {
  int row = blockIdx.x; int e = threadIdx.x;
  float v = g_conv[row*E2c + e] + cb[e];
  float s1 = v, s2 = v*v;
  blk_reduce2(s1, s2);
  float mu = s1 * (1.f/E2c);
  float var = s2 * (1.f/E2c) - mu*mu;
  g_h[row*E2c + e] = gelu_f((v - mu) * rsqrtf(var + 1e-5f) * ls[e] + lo[e]);
}

// ---------------- generic fp32 SIMT GEMM (small mats) ----------------------
#define BM 64
#define BN 64
#define BK 16
__global__ void k_gemm(const float* __restrict__ A, const float* __restrict__ W,
                       const float* __restrict__ bias, const float* res,
                       float* C, int M, int N, int K, int act) {
  __shared__ float As[BK][BM+1];
  __shared__ float Bs[BK][BN];
  int bn = blockIdx.x * BN, bm = blockIdx.y * BM;
  int tid = threadIdx.x;
  int tx = tid & 15, ty = tid >> 4;
  float acc[4][4];
  #pragma unroll
  for (int i = 0; i < 4; i++)
    #pragma unroll
    for (int j = 0; j < 4; j++) acc[i][j] = 0.f;
  for (int k0 = 0; k0 < K; k0 += BK) {
    #pragma unroll
    for (int i = 0; i < 4; i++) {
      int idx = tid + i*256;
      int m = idx >> 4, kk = idx & 15;
      As[kk][m] = A[(bm + m)*K + k0 + kk];
    }
    #pragma unroll
    for (int i = 0; i < 4; i++) {
      int idx = tid + i*256;
      int kk = idx >> 6, n = idx & 63;
      Bs[kk][n] = W[(k0 + kk)*N + bn + n];
    }
    __syncthreads();
    #pragma unroll
    for (int kk = 0; kk < BK; kk++) {
      float a[4], bb[4];
      #pragma unroll
      for (int i = 0; i < 4; i++) a[i] = As[kk][ty*4 + i];
      #pragma unroll
      for (int j = 0; j < 4; j++) bb[j] = Bs[kk][tx*4 + j];
      #pragma unroll
      for (int i = 0; i < 4; i++)
        #pragma unroll
        for (int j = 0; j < 4; j++) acc[i][j] = fmaf(a[i], bb[j], acc[i][j]);
    }
    __syncthreads();
  }
  #pragma unroll
  for (int i = 0; i < 4; i++) {
    int m = bm + ty*4 + i;
    #pragma unroll
    for (int j = 0; j < 4; j++) {
      int n = bn + tx*4 + j;
      float c = acc[i][j] + bias[n];
      if (act == 1) c = gelu_f(c);
      if (res) c += res[(size_t)m*N + n];
      C[(size_t)m*N + n] = c;
    }
  }
}

// ---------------- mass head ------------------------------------------------
__global__ void k_mass(const float* __restrict__ mw, const float* __restrict__ mb) {
  __shared__ float hs[32][E2c+1];
  __shared__ float ws[E2c*Hc];
  int r0 = blockIdx.x * 32;
  int tid = threadIdx.x;
  for (int idx = tid; idx < 32*E2c; idx += 256) {
    int r = idx / E2c, k = idx - (idx / E2c)*E2c;
    hs[r][k] = g_h[(r0 + r)*E2c + k];
  }
  for (int idx = tid; idx < E2c*Hc; idx += 256) ws[idx] = mw[idx];
  __syncthreads();
  int r = tid >> 3, hh = tid & 7;
  float acc = mb[hh];
  #pragma unroll 4
  for (int k = 0; k < E2c; k++) acc = fmaf(hs[r][k], ws[k*Hc + hh], acc);
  int row = r0 + r; int b = row >> 6, s = row & 63;
  g_mass[(b*Hc + hh)*Sc + s] = softplus_f(acc);
}

// ---------------- gravity attention core -----------------------------------
__global__ void k_attn() {
  int bh = blockIdx.x; int b = bh >> 3, hh = bh & 7;
  int i = threadIdx.x;
  __shared__ float qs[Sc][Dc+1];
  __shared__ float vs[Sc][Dc+1];
  __shared__ float ms[Sc];
  __shared__ float sq[Sc];
  const float* qbase = g_qk + (size_t)(b*Sc)*E2c + hh*Dc;
  const float* vbase = g_v  + (size_t)(b*Sc)*E2c + hh*Dc;
  float qi[Dc];
  float ssq = 0.f;
  #pragma unroll
  for (int d = 0; d < Dc; d++) {
    float q = qbase[i*E2c + d];
    qs[i][d] = q; qi[d] = q; ssq = fmaf(q, q, ssq);
    vs[i][d] = vbase[i*E2c + d];
  }
  sq[i] = ssq;
  ms[i] = g_mass[(b*Hc + hh)*Sc + i];
  __syncthreads();
  float mi = ms[i];
  float mmax = -INFINITY, l = 0.f;
  float acc[Dc];
  #pragma unroll
  for (int d = 0; d < Dc; d++) acc[d] = 0.f;
  for (int j = 0; j < Sc; j++) {
    float dot = 0.f;
    #pragma unroll
    for (int d = 0; d < Dc; d++) dot = fmaf(qi[d], qs[j][d], dot);
    float d2 = fmaxf(ssq + sq[j] - 2.f*dot, 0.f) + 1e-6f;
    float sc = mi * ms[j] / d2;
    float mn = fmaxf(mmax, sc);
    float scale = __expf(mmax - mn);
    float p = __expf(sc - mn);
    l = l*scale + p;
    #pragma unroll
    for (int d = 0; d < Dc; d++) acc[d] = fmaf(p, vs[j][d], acc[d]*scale);
    mmax = mn;
  }
  float inv = 1.f / l;
  float* obase = g_att + (size_t)(b*Sc + i)*E2c + hh*Dc;
  #pragma unroll
  for (int d = 0; d < Dc; d++) obase[d] = acc[d] * inv;
}

// ---------------- residual + LN + gelu -------------------------------------
__global__ void k_res_ln_gelu(const float* __restrict__ ls, const float* __restrict__ lo) {
  int row = blockIdx.x; int e = threadIdx.x;
  float v = g_h[row*E2c + e] + g_att[row*E2c + e];
  float s1 = v, s2 = v*v;
  blk_reduce2(s1, s2);
  float mu = s1 * (1.f/E2c);
  float var = s2 * (1.f/E2c) - mu*mu;
  g_h[row*E2c + e] = gelu_f((v - mu) * rsqrtf(var + 1e-5f) * ls[e] + lo[e]);
}

// ---------------- fc activation hi/lo split --------------------------------
__global__ void k_split() {
  int i = blockIdx.x * 256 + threadIdx.x;
  float v = g_h[i];
  __nv_bfloat16 hi = __float2bfloat16(v);
  __nv_bfloat16 lo = __float2bfloat16(v - __bfloat162float(hi));
  g_Ah[i] = hi;
  g_Al[i] = lo;
}

// ---------------- fc GEMM on mma.sync (bf16 hi/lo x3 products) -------------
// D[128, 96-slab] = A[128,12288] @ W[12288,12288], fp32 accum.
// grid=128 CTAs, 256 thr (8 warps, 4x2), BK=32 double-buffered smem.
// Smem word layout per buffer (7168 words = 28KB):
//   Ah [kstep2][mt8][128w] @0      Al @2048
//   Wh [kstep2][nt12][64w] @4096   Wl @5632
#define FC_BN 96
#define FC_BK 32
#define FC_ITERS (FLATc/FC_BK)      // 384
#define FC_BUFW 7168
#define FC_SMEM (2*FC_BUFW*4)       // 57344 B

#define MMA16816(d, a, b) \
  asm volatile("mma.sync.aligned.m16n8k16.row.col.f32.bf16.bf16.f32 " \
    "{%0,%1,%2,%3}, {%4,%5,%6,%7}, {%8,%9}, {%0,%1,%2,%3};" \
    : "+f"((d)[0]), "+f"((d)[1]), "+f"((d)[2]), "+f"((d)[3]) \
    : "r"((a).x), "r"((a).y), "r"((a).z), "r"((a).w), "r"((b).x), "r"((b).y))

__device__ __forceinline__ uint32_t pack_bf16(float lo16, float hi16) {
  __nv_bfloat16 a = __float2bfloat16(lo16);
  __nv_bfloat16 b = __float2bfloat16(hi16);
  return ((uint32_t)__bfloat16_as_ushort(b) << 16) | __bfloat16_as_ushort(a);
}

__global__ void __launch_bounds__(256, 1) k_fc_mma(const float* __restrict__ W,
                                                   const float* __restrict__ bias) {
  extern __shared__ uint32_t sm[];
  int tid = threadIdx.x;
  int lane = tid & 31, wp = tid >> 5;
  int warpM = wp >> 1, warpN = wp & 1;
  int n0 = blockIdx.x * FC_BN;

  // A loader mapping: thread -> (row m, 16k half)
  int lm = tid >> 1, lhalf = tid & 1;
  int lmt = lm >> 4, lr = lm & 15;
  int lg = lr & 7, lridx = lr >> 3;
  // W loader mapping: k-pair kp (0..15), n-chunk nc (0..15) of 6
  int lkp = tid >> 4, lnc = tid & 15;
  int wkstep = lkp >> 3, wp8 = lkp & 7;
  int wq = wp8 & 3, wbidx = wp8 >> 2;

  float acc[2][6][4];
  #pragma unroll
  for (int i = 0; i < 2; i++)
    #pragma unroll
    for (int j = 0; j < 6; j++)
      #pragma unroll
      for (int c = 0; c < 4; c++) acc[i][j][c] = 0.f;

  uint4 rAh[2], rAl[2];
  float rw0[6], rw1[6];

  const __nv_bfloat16* gah = g_Ah + (size_t)lm*FLATc + lhalf*16;
  const __nv_bfloat16* gal = g_Al + (size_t)lm*FLATc + lhalf*16;

  // ---- prologue load (iter 0) ----
  {
    rAh[0] = ((const uint4*)gah)[0]; rAh[1] = ((const uint4*)gah)[1];
    rAl[0] = ((const uint4*)gal)[0]; rAl[1] = ((const uint4*)gal)[1];
    const float* w0 = W + (size_t)(2*lkp)*FLATc + n0 + lnc*6;
    const float* w1 = w0 + FLATc;
    #pragma unroll
    for (int j = 0; j < 3; j++) {
      float2 v0 = ((const float2*)w0)[j];
      float2 v1 = ((const float2*)w1)[j];
      rw0[2*j] = v0.x; rw0[2*j+1] = v0.y;
      rw1[2*j] = v1.x; rw1[2*j+1] = v1.y;
    }
  }
  // ---- prologue store (buf 0) ----
  {
    uint32_t* base = sm;
    uint32_t* ah = base + (lhalf*8 + lmt)*128;
    uint32_t* al = ah + 2048;
    const uint32_t* vh = (const uint32_t*)rAh;
    const uint32_t* vl = (const uint32_t*)rAl;
    #pragma unroll
    for (int p = 0; p < 8; p++) {
      int q = p & 3, aidx = lridx + 2*(p >> 2);
      int off = (lg*4 + q)*4 + aidx;
      ah[off] = vh[p];
      al[off] = vl[p];
    }
    #pragma unroll
    for (int j = 0; j < 6; j++) {
      int n = lnc*6 + j;
      int nt = n >> 3, g = n & 7;
      uint32_t off = 4096 + (uint32_t)(wkstep*12 + nt)*64 + (g*4 + wq)*2 + wbidx;
      float h0 = __bfloat162float(__float2bfloat16(rw0[j]));
      float h1 = __bfloat162float(__float2bfloat16(rw1[j]));
      base[off]        = pack_bf16(h0, h1);
      base[off + 1536] = pack_bf16(rw0[j] - h0, rw1[j] - h1);
    }
  }
  __syncthreads();

  for (int it = 0; it < FC_ITERS; it++) {
    int buf = it & 1;
    // ---- load next into regs ----
    if (it + 1 < FC_ITERS) {
      size_t k0 = (size_t)(it + 1) * FC_BK;
      rAh[0] = ((const uint4*)(gah + k0))[0]; rAh[1] = ((const uint4*)(gah + k0))[1];
      rAl[0] = ((const uint4*)(gal + k0))[0]; rAl[1] = ((const uint4*)(gal + k0))[1];
      const float* w0 = W + (k0 + 2*lkp)*(size_t)FLATc + n0 + lnc*6;
      const float* w1 = w0 + FLATc;
      #pragma unroll
      for (int j = 0; j < 3; j++) {
        float2 v0 = ((const float2*)w0)[j];
        float2 v1 = ((const float2*)w1)[j];
        rw0[2*j] = v0.x; rw0[2*j+1] = v0.y;
        rw1[2*j] = v1.x; rw1[2*j+1] = v1.y;
      }
    }
    // ---- compute on buf ----
    {
      uint32_t* base = sm + buf*FC_BUFW;
      #pragma unroll
      for (int ks = 0; ks < 2; ks++) {
        uint4 fah[2], fal[2];
        #pragma unroll
        for (int i = 0; i < 2; i++) {
          int mt = warpM*2 + i;
          fah[i] = *(const uint4*)(base + (ks*8 + mt)*128 + lane*4);
          fal[i] = *(const uint4*)(base + 2048 + (ks*8 + mt)*128 + lane*4);
        }
        uint2 fwh[6], fwl[6];
        #pragma unroll
        for (int j = 0; j < 6; j++) {
          int nt = warpN*6 + j;
          fwh[j] = *(const uint2*)(base + 4096 + (ks*12 + nt)*64 + lane*2);
          fwl[j] = *(const uint2*)(base + 5632 + (ks*12 + nt)*64 + lane*2);
        }
        #pragma unroll
        for (int i = 0; i < 2; i++)
          #pragma unroll
          for (int j = 0; j < 6; j++) MMA16816(acc[i][j], fah[i], fwh[j]);
        #pragma unroll
        for (int i = 0; i < 2; i++)
          #pragma unroll
          for (int j = 0; j < 6; j++) MMA16816(acc[i][j], fal[i], fwh[j]);
        #pragma unroll
        for (int i = 0; i < 2; i++)
          #pragma unroll
          for (int j = 0; j < 6; j++) MMA16816(acc[i][j], fah[i], fwl[j]);
      }
    }
    // ---- store next into other buf ----
    if (it + 1 < FC_ITERS) {
      uint32_t* base = sm + ((it + 1) & 1)*FC_BUFW;
      uint32_t* ah = base + (lhalf*8 + lmt)*128;
      uint32_t* al = ah + 2048;
      const uint32_t* vh = (const uint32_t*)rAh;
      const uint32_t* vl = (const uint32_t*)rAl;
      #pragma unroll
      for (int p = 0; p < 8; p++) {
        int q = p & 3, aidx = lridx + 2*(p >> 2);
        int off = (lg*4 + q)*4 + aidx;
        ah[off] = vh[p];
        al[off] = vl[p];
      }
      #pragma unroll
      for (int j = 0; j < 6; j++) {
        int n = lnc*6 + j;
        int nt = n >> 3, g = n & 7;
        uint32_t off = 4096 + (uint32_t)(wkstep*12 + nt)*64 + (g*4 + wq)*2 + wbidx;
        float h0 = __bfloat162float(__float2bfloat16(rw0[j]));
        float h1 = __bfloat162float(__float2bfloat16(rw1[j]));
        base[off]        = pack_bf16(h0, h1);
        base[off + 1536] = pack_bf16(rw0[j] - h0, rw1[j] - h1);
      }
    }
    __syncthreads();
  }

  // ---- epilogue: bias + gelu -> g_f ----
  int g = lane >> 2, q = lane & 3;
  #pragma unroll
  for (int i = 0; i < 2; i++) {
    int m = warpM*32 + i*16 + g;
    #pragma unroll
    for (int j = 0; j < 6; j++) {
      int n = n0 + warpN*48 + j*8 + q*2;
      float b0 = bias[n], b1 = bias[n+1];
      float2 r0, r1;
      r0.x = gelu_f(acc[i][j][0] + b0);
      r0.y = gelu_f(acc[i][j][1] + b1);
      r1.x = gelu_f(acc[i][j][2] + b0);
      r1.y = gelu_f(acc[i][j][3] + b1);
      *(float2*)(g_f + (size_t)m*FLATc + n)       = r0;
      *(float2*)(g_f + (size_t)(m + 8)*FLATc + n) = r1;
    }
  }
}

// ---------------- LN over FLAT ---------------------------------------------
__global__ void k_ln_flat(const float* __restrict__ ls, const float* __restrict__ lo) {
  int b = blockIdx.x; int t = threadIdx.x;
  float* frow = g_f + (size_t)b*FLATc;
  float s1 = 0.f, s2 = 0.f;
  for (int k = t; k < FLATc; k += 256) { float v = frow[k]; s1 += v; s2 += v*v; }
  blk_reduce2(s1, s2);
  float mu = s1 * (1.f/FLATc);
  float var = s2 * (1.f/FLATc) - mu*mu;
  float rs = rsqrtf(var + 1e-5f);
  for (int k = t; k < FLATc; k += 256) {
    float v = frow[k];
    frow[k] = (v - mu) * rs * ls[k] + lo[k];
  }
}

// ---------------- final out GEMM -------------------------------------------
__global__ void k_out(const float* __restrict__ ow, const float* __restrict__ ob,
                      float* __restrict__ out) {
  int o = blockIdx.x, b = blockIdx.y;
  int t = threadIdx.x;
  const float* frow = g_f + (size_t)b*FLATc;
  float s1 = 0.f, s2 = 0.f;
  for (int k = t; k < FLATc; k += 256) s1 = fmaf(frow[k], ow[(size_t)k*HORc + o], s1);
  blk_reduce2(s1, s2);
  if (t == 0) out[b*HORc + o] = s1 + ob[o];
}

// ---------------- launch ----------------------------------------------------
extern "C" void kernel_launch(void* const* d_in, const int* in_sizes, int n_in,
                              void* d_out, int out_size) {
  const float* x      = (const float*)d_in[0];
  const float* proj_w = (const float*)d_in[1];
  const float* proj_b = (const float*)d_in[2];
  const float* ln0_s  = (const float*)d_in[3];
  const float* ln0_o  = (const float*)d_in[4];
  const float* conv_w = (const float*)d_in[5];
  const float* conv_b = (const float*)d_in[6];
  const float* ln1_s  = (const float*)d_in[7];
  const float* ln1_o  = (const float*)d_in[8];
  const float* qk_w   = (const float*)d_in[9];
  const float* qk_b   = (const float*)d_in[10];
  const float* mass_w = (const float*)d_in[11];
  const float* mass_b = (const float*)d_in[12];
  const float* v_w    = (const float*)d_in[13];
  const float* v_b    = (const float*)d_in[14];
  const float* norm_s = (const float*)d_in[15];
  const float* norm_o = (const float*)d_in[16];
  const float* mlp_w1 = (const float*)d_in[17];
  const float* mlp_b1 = (const float*)d_in[18];
  const float* mlp_w2 = (const float*)d_in[19];
  const float* mlp_b2 = (const float*)d_in[20];
  const float* fc_w   = (const float*)d_in[21];
  const float* fc_b   = (const float*)d_in[22];
  const float* ln2_s  = (const float*)d_in[23];
  const float* ln2_o  = (const float*)d_in[24];
  const float* out_w  = (const float*)d_in[25];
  const float* out_b  = (const float*)d_in[26];

  float *p_h, *p_qk, *p_v, *p_mlp;
  cudaGetSymbolAddress((void**)&p_h,   g_h);
  cudaGetSymbolAddress((void**)&p_qk,  g_qk);
  cudaGetSymbolAddress((void**)&p_v,   g_v);
  cudaGetSymbolAddress((void**)&p_mlp, g_mlp);

  cudaFuncSetAttribute(k_fc_mma, cudaFuncAttributeMaxDynamicSharedMemorySize, FC_SMEM);

  k_proj<<<ROWS, Ec>>>(x, proj_w, proj_b, ln0_s, ln0_o);
  k_conv<<<dim3(4, Bc), E2c>>>(conv_w);
  k_ln_gelu_conv<<<ROWS, E2c>>>(conv_b, ln1_s, ln1_o);

  for (int l = 0; l < Lc; l++) {
    k_gemm<<<dim3(E2c/BN, ROWS/BM), 256>>>(p_h, qk_w + (size_t)l*E2c*E2c,
                                           qk_b + l*E2c, nullptr, p_qk,
                                           ROWS, E2c, E2c, 0);
    k_gemm<<<dim3(E2c/BN, ROWS/BM), 256>>>(p_h, v_w + (size_t)l*E2c*E2c,
                                           v_b + l*E2c, nullptr, p_v,
                                           ROWS, E2c, E2c, 0);
    k_mass<<<ROWS/32, 256>>>(mass_w + (size_t)l*E2c*Hc, mass_b + l*Hc);
    k_attn<<<Bc*Hc, Sc>>>();
    k_res_ln_gelu<<<ROWS, E2c>>>(norm_s + l*E2c, norm_o + l*E2c);
  }

  k_gemm<<<dim3(MLPH/BN, ROWS/BM), 256>>>(p_h, mlp_w1, mlp_b1, nullptr, p_mlp,
                                          ROWS, MLPH, E2c, 1);
  k_gemm<<<dim3(E2c/BN, ROWS/BM), 256>>>(p_mlp, mlp_w2, mlp_b2, p_h, p_h,
                                         ROWS, E2c, MLPH, 0);

  k_split<<<(Bc*FLATc)/256, 256>>>();
  k_fc_mma<<<FLATc/FC_BN, 256, FC_SMEM>>>(fc_w, fc_b);
  k_ln_flat<<<Bc, 256>>>(ln2_s, ln2_o);
  k_out<<<dim3(HORc, Bc), 256>>>(out_w, out_b, (float*)d_out);
}

// round 4
// speedup vs baseline: 1.4937x; 1.0909x over previous
#include <cuda_runtime.h>
#include <cuda_bf16.h>
#include <math.h>
#include <stdint.h>

#define Bc 128
#define Sc 64
#define FIN 32
#define Ec 96
#define E2c 192
#define Hc 8
#define Dc 24
#define Lc 4
#define HORc 24
#define FLATc (Sc*E2c)          // 12288
#define ROWS (Bc*Sc)            // 8192
#define MLPH (4*Ec)             // 384

// ---------------- scratch (static device globals; no allocation) ----------
__device__ float g_h0[ROWS*Ec];
__device__ float g_conv[ROWS*E2c];
__device__ float g_h[ROWS*E2c];
__device__ float g_qk[ROWS*E2c];
__device__ float g_v[ROWS*E2c];
__device__ float g_mass[Bc*Hc*Sc];
__device__ float g_att[ROWS*E2c];
__device__ float g_mlp[ROWS*MLPH];
__device__ float g_f[Bc*FLATc];
__device__ __nv_bfloat16 g_Ah[Bc*FLATc];        // fc activations hi
__device__ __nv_bfloat16 g_Al[Bc*FLATc];        // fc activations lo
__device__ __nv_bfloat16 g_Wh[FLATc*FLATc];     // fc weights hi (302MB)
__device__ __nv_bfloat16 g_Wl[FLATc*FLATc];     // fc weights lo (302MB)

// ---------------- helpers ---------------------------------------------------
__device__ __forceinline__ uint32_t smem_u32(const void* p) {
  uint32_t a;
  asm("{ .reg .u64 t; cvta.to.shared.u64 t, %1; cvt.u32.u64 %0, t; }" : "=r"(a) : "l"(p));
  return a;
}
__device__ __forceinline__ float gelu_f(float x) {
  float t = tanhf(0.7978845608028654f * (x + 0.044715f * x * x * x));
  return 0.5f * x * (1.f + t);
}
__device__ __forceinline__ float softplus_f(float x) {
  return fmaxf(x, 0.f) + log1pf(expf(-fabsf(x)));
}
__device__ __forceinline__ void blk_reduce2(float& a, float& b) {
  __shared__ float ra[256], rb[256];
  int t = threadIdx.x, n = blockDim.x;
  ra[t] = a; rb[t] = b;
  __syncthreads();
  #pragma unroll
  for (int s = 128; s > 0; s >>= 1) {
    if (t < s && t + s < n) { ra[t] += ra[t+s]; rb[t] += rb[t+s]; }
    __syncthreads();
  }
  a = ra[0]; b = rb[0];
}
__device__ __forceinline__ void split2(float a, float b, uint32_t& ph, uint32_t& pl) {
  __nv_bfloat16 ha = __float2bfloat16(a), hb = __float2bfloat16(b);
  float ra = a - __bfloat162float(ha), rb = b - __bfloat162float(hb);
  ph = ((uint32_t)__bfloat16_as_ushort(hb) << 16) | __bfloat16_as_ushort(ha);
  pl = ((uint32_t)__bfloat16_as_ushort(__float2bfloat16(rb)) << 16)
       | __bfloat16_as_ushort(__float2bfloat16(ra));
}

// ---------------- stage 1: proj -> LN -> gelu -------------------------------
__global__ void k_proj(const float* __restrict__ x, const float* __restrict__ w,
                       const float* __restrict__ bias, const float* __restrict__ ls,
                       const float* __restrict__ lo) {
  int row = blockIdx.x;
  int e = threadIdx.x;
  __shared__ float xs[FIN];
  if (e < FIN) xs[e] = x[row*FIN + e];
  __syncthreads();
  float acc = bias[e];
  #pragma unroll
  for (int k = 0; k < FIN; k++) acc = fmaf(xs[k], w[k*Ec + e], acc);
  float s1 = acc, s2 = acc*acc;
  blk_reduce2(s1, s2);
  float mu = s1 * (1.f/Ec);
  float var = s2 * (1.f/Ec) - mu*mu;
  float y = (acc - mu) * rsqrtf(var + 1e-5f) * ls[e] + lo[e];
  g_h0[row*Ec + e] = gelu_f(y);
}

// ---------------- stage 2: 4x4 SAME conv ------------------------------------
__global__ void k_conv(const float* __restrict__ cw) {
  int i  = blockIdx.y;
  int j0 = blockIdx.x * 16;
  int oc = threadIdx.x;
  __shared__ float sp[4][19*Ec];
  for (int idx = oc; idx < 4*19*Ec; idx += E2c) {
    int di  = idx / (19*Ec);
    int rem = idx - di*19*Ec;
    int col = rem / Ec;
    int c   = rem - col*Ec;
    int gi = i - 1 + di;
    int gj = j0 - 1 + col;
    float v = 0.f;
    if (gi >= 0 && gi < Bc && gj >= 0 && gj < Sc)
      v = g_h0[(gi*Sc + gj)*Ec + c];
    sp[di][col*Ec + c] = v;
  }
  __syncthreads();
  float acc[16];
  #pragma unroll
  for (int j = 0; j < 16; j++) acc[j] = 0.f;
  for (int di = 0; di < 4; di++) {
    for (int c = 0; c < Ec; c++) {
      float pv[19];
      #pragma unroll
      for (int t = 0; t < 19; t++) pv[t] = sp[di][t*Ec + c];
      #pragma unroll
      for (int dj = 0; dj < 4; dj++) {
        float wv = cw[((di*4 + dj)*Ec + c)*E2c + oc];
        #pragma unroll
        for (int j = 0; j < 16; j++) acc[j] = fmaf(pv[j + dj], wv, acc[j]);
      }
    }
  }
  #pragma unroll
  for (int j = 0; j < 16; j++)
    g_conv[(i*Sc + j0 + j)*E2c + oc] = acc[j];
}

// ---------------- stage 3: conv bias -> LN -> gelu --------------------------
__global__ void k_ln_gelu_conv(const float* __restrict__ cb,
                               const float* __restrict__ ls, const float* __restrict__ lo) {
  int row = blockIdx.x; int e = threadIdx.x;
  float v = g_conv[row*E2c + e] + cb[e];
  float s1 = v, s2 = v*v;
  blk_reduce2(s1, s2);
  float mu = s1 * (1.f/E2c);
  float var = s2 * (1.f/E2c) - mu*mu;
  g_h[row*E2c + e] = gelu_f((v - mu) * rsqrtf(var + 1e-5f) * ls[e] + lo[e]);
}

// ---------------- generic fp32 SIMT GEMM (small mats) ------------------------
#define BM 64
#define BN 64
#define BK 16
__global__ void k_gemm(const float* __restrict__ A, const float* __restrict__ W,
                       const float* __restrict__ bias, const float* res,
                       float* C, int M, int N, int K, int act) {
  __shared__ float As[BK][BM+1];
  __shared__ float Bs[BK][BN];
  int bn = blockIdx.x * BN, bm = blockIdx.y * BM;
  int tid = threadIdx.x;
  int tx = tid & 15, ty = tid >> 4;
  float acc[4][4];
  #pragma unroll
  for (int i = 0; i < 4; i++)
    #pragma unroll
    for (int j = 0; j < 4; j++) acc[i][j] = 0.f;
  for (int k0 = 0; k0 < K; k0 += BK) {
    #pragma unroll
    for (int i = 0; i < 4; i++) {
      int idx = tid + i*256;
      int m = idx >> 4, kk = idx & 15;
      As[kk][m] = A[(bm + m)*K + k0 + kk];
    }
    #pragma unroll
    for (int i = 0; i < 4; i++) {
      int idx = tid + i*256;
      int kk = idx >> 6, n = idx & 63;
      Bs[kk][n] = W[(k0 + kk)*N + bn + n];
    }
    __syncthreads();
    #pragma unroll
    for (int kk = 0; kk < BK; kk++) {
      float a[4], bb[4];
      #pragma unroll
      for (int i = 0; i < 4; i++) a[i] = As[kk][ty*4 + i];
      #pragma unroll
      for (int j = 0; j < 4; j++) bb[j] = Bs[kk][tx*4 + j];
      #pragma unroll
      for (int i = 0; i < 4; i++)
        #pragma unroll
        for (int j = 0; j < 4; j++) acc[i][j] = fmaf(a[i], bb[j], acc[i][j]);
    }
    __syncthreads();
  }
  #pragma unroll
  for (int i = 0; i < 4; i++) {
    int m = bm + ty*4 + i;
    #pragma unroll
    for (int j = 0; j < 4; j++) {
      int n = bn + tx*4 + j;
      float c = acc[i][j] + bias[n];
      if (act == 1) c = gelu_f(c);
      if (res) c += res[(size_t)m*N + n];
      C[(size_t)m*N + n] = c;
    }
  }
}

// ---------------- mass head --------------------------------------------------
__global__ void k_mass(const float* __restrict__ mw, const float* __restrict__ mb) {
  __shared__ float hs[32][E2c+1];
  __shared__ float ws[E2c*Hc];
  int r0 = blockIdx.x * 32;
  int tid = threadIdx.x;
  for (int idx = tid; idx < 32*E2c; idx += 256) {
    int r = idx / E2c, k = idx - (idx / E2c)*E2c;
    hs[r][k] = g_h[(r0 + r)*E2c + k];
  }
  for (int idx = tid; idx < E2c*Hc; idx += 256) ws[idx] = mw[idx];
  __syncthreads();
  int r = tid >> 3, hh = tid & 7;
  float acc = mb[hh];
  #pragma unroll 4
  for (int k = 0; k < E2c; k++) acc = fmaf(hs[r][k], ws[k*Hc + hh], acc);
  int row = r0 + r; int b = row >> 6, s = row & 63;
  g_mass[(b*Hc + hh)*Sc + s] = softplus_f(acc);
}

// ---------------- gravity attention core -------------------------------------
__global__ void k_attn() {
  int bh = blockIdx.x; int b = bh >> 3, hh = bh & 7;
  int i = threadIdx.x;
  __shared__ float qs[Sc][Dc+1];
  __shared__ float vs[Sc][Dc+1];
  __shared__ float ms[Sc];
  __shared__ float sq[Sc];
  const float* qbase = g_qk + (size_t)(b*Sc)*E2c + hh*Dc;
  const float* vbase = g_v  + (size_t)(b*Sc)*E2c + hh*Dc;
  float qi[Dc];
  float ssq = 0.f;
  #pragma unroll
  for (int d = 0; d < Dc; d++) {
    float q = qbase[i*E2c + d];
    qs[i][d] = q; qi[d] = q; ssq = fmaf(q, q, ssq);
    vs[i][d] = vbase[i*E2c + d];
  }
  sq[i] = ssq;
  ms[i] = g_mass[(b*Hc + hh)*Sc + i];
  __syncthreads();
  float mi = ms[i];
  float mmax = -INFINITY, l = 0.f;
  float acc[Dc];
  #pragma unroll
  for (int d = 0; d < Dc; d++) acc[d] = 0.f;
  for (int j = 0; j < Sc; j++) {
    float dot = 0.f;
    #pragma unroll
    for (int d = 0; d < Dc; d++) dot = fmaf(qi[d], qs[j][d], dot);
    float d2 = fmaxf(ssq + sq[j] - 2.f*dot, 0.f) + 1e-6f;
    float sc = mi * ms[j] / d2;
    float mn = fmaxf(mmax, sc);
    float scale = __expf(mmax - mn);
    float p = __expf(sc - mn);
    l = l*scale + p;
    #pragma unroll
    for (int d = 0; d < Dc; d++) acc[d] = fmaf(p, vs[j][d], acc[d]*scale);
    mmax = mn;
  }
  float inv = 1.f / l;
  float* obase = g_att + (size_t)(b*Sc + i)*E2c + hh*Dc;
  #pragma unroll
  for (int d = 0; d < Dc; d++) obase[d] = acc[d] * inv;
}

// ---------------- residual + LN + gelu ---------------------------------------
__global__ void k_res_ln_gelu(const float* __restrict__ ls, const float* __restrict__ lo) {
  int row = blockIdx.x; int e = threadIdx.x;
  float v = g_h[row*E2c + e] + g_att[row*E2c + e];
  float s1 = v, s2 = v*v;
  blk_reduce2(s1, s2);
  float mu = s1 * (1.f/E2c);
  float var = s2 * (1.f/E2c) - mu*mu;
  g_h[row*E2c + e] = gelu_f((v - mu) * rsqrtf(var + 1e-5f) * ls[e] + lo[e]);
}

// ---------------- fc activation hi/lo split ----------------------------------
__global__ void k_split() {
  int i = blockIdx.x * 256 + threadIdx.x;
  float v = g_h[i];
  __nv_bfloat16 hi = __float2bfloat16(v);
  __nv_bfloat16 lo = __float2bfloat16(v - __bfloat162float(hi));
  g_Ah[i] = hi;
  g_Al[i] = lo;
}

// ---------------- fc weight hi/lo pre-conversion -----------------------------
// 150,994,944 floats; 4 per thread; grid = 147456 x 256.
__global__ void k_convW(const float* __restrict__ W) {
  size_t i = ((size_t)blockIdx.x * 256 + threadIdx.x) * 4;
  float4 v = *(const float4*)(W + i);
  uint2 ph, pl;
  split2(v.x, v.y, ph.x, pl.x);
  split2(v.z, v.w, ph.y, pl.y);
  *(uint2*)(g_Wh + i) = ph;
  *(uint2*)(g_Wl + i) = pl;
}

// ---------------- fc GEMM: cp.async 4-stage + ldmatrix + bf16 mma ------------
// D[128, 96-slab] = A[128,12288] @ W[12288,12288]; 3-product hi/lo compensation.
// grid=128 CTAs, 256 thr (8 warps = 4m x 2n), warp tile 32m x 48n.
#define FC_BN 96
#define FC_BK 32
#define FC_IT (FLATc/FC_BK)     // 384
#define FC_ST 4
#define A_PAD 80                // 4x16B chunks padded to 5 -> conflict-free LDSM
#define W_PAD 208               // 12x16B chunks padded to 13 -> conflict-free LDSM
#define OFF_AL 10240            // 128*80
#define OFF_WH 20480
#define OFF_WL 27136            // +32*208
#define ST_SZ  33792
#define FC_SMEM (FC_ST*ST_SZ)   // 135168

#define MMA16816(d, a, b) \
  asm volatile("mma.sync.aligned.m16n8k16.row.col.f32.bf16.bf16.f32 " \
    "{%0,%1,%2,%3}, {%4,%5,%6,%7}, {%8,%9}, {%0,%1,%2,%3};" \
    : "+f"((d)[0]), "+f"((d)[1]), "+f"((d)[2]), "+f"((d)[3]) \
    : "r"((a).x), "r"((a).y), "r"((a).z), "r"((a).w), "r"((b).x), "r"((b).y))

__device__ __forceinline__ void cp16(uint32_t d, const void* s) {
  asm volatile("cp.async.cg.shared.global [%0], [%1], 16;" :: "r"(d), "l"(s));
}

__device__ __forceinline__ void fc_stage_load(uint32_t sb, int slot, int k0, int n0, int tid) {
  uint32_t st = sb + slot*ST_SZ;
  // A hi/lo: 512 16B-chunks each (128 rows x 4 chunks)
  {
    int g0 = tid * 2;
    #pragma unroll
    for (int t = 0; t < 2; t++) {
      int g = g0 + t;
      int m = g >> 2, c = g & 3;
      uint32_t d = st + m*A_PAD + c*16;
      size_t src = (size_t)m*FLATc + k0 + c*8;
      cp16(d, g_Ah + src);
      cp16(d + OFF_AL, g_Al + src);
    }
  }
  // W hi/lo: 384 chunks each (32 k-rows x 12 chunks) -> 768 over 256 threads
  #pragma unroll
  for (int t = 0; t < 3; t++) {
    int g = tid + t*256;
    int half = (g >= 384) ? 1 : 0;
    int r = g - half*384;
    int k = r / 12, c = r - k*12;
    uint32_t d = st + OFF_WH + half*(OFF_WL - OFF_WH) + k*W_PAD + c*16;
    size_t src = (size_t)(k0 + k)*FLATc + n0 + c*8;
    cp16(d, (half ? g_Wl : g_Wh) + src);
  }
}

__global__ void __launch_bounds__(256, 1) k_fc_mma(const float* __restrict__ bias) {
  extern __shared__ char smc[];
  uint32_t sb = smem_u32(smc);
  int tid = threadIdx.x, lane = tid & 31, wp = tid >> 5;
  int warpM = wp >> 1, warpN = wp & 1;
  int n0 = blockIdx.x * FC_BN;

  float acc[2][6][4];
  #pragma unroll
  for (int i = 0; i < 2; i++)
    #pragma unroll
    for (int j = 0; j < 6; j++)
      #pragma unroll
      for (int c = 0; c < 4; c++) acc[i][j][c] = 0.f;

  #pragma unroll
  for (int s = 0; s < FC_ST - 1; s++) {
    fc_stage_load(sb, s, s*FC_BK, n0, tid);
    asm volatile("cp.async.commit_group;" ::: "memory");
  }

  int arow = warpM*32 + (lane & 15);

  for (int it = 0; it < FC_IT; it++) {
    asm volatile("cp.async.wait_group 2;" ::: "memory");
    __syncthreads();
    if (it + FC_ST - 1 < FC_IT) {
      fc_stage_load(sb, (it + FC_ST - 1) & 3, (it + FC_ST - 1)*FC_BK, n0, tid);
    }
    asm volatile("cp.async.commit_group;" ::: "memory");

    uint32_t st = sb + (it & 3)*ST_SZ;
    #pragma unroll
    for (int ks = 0; ks < 2; ks++) {
      uint4 fah[2], fal[2];
      int c = ks*2 + (lane >> 4);
      #pragma unroll
      for (int i = 0; i < 2; i++) {
        uint32_t ad = st + (uint32_t)(arow + i*16)*A_PAD + c*16;
        asm volatile("ldmatrix.sync.aligned.m8n8.x4.shared.b16 {%0,%1,%2,%3}, [%4];"
          : "=r"(fah[i].x), "=r"(fah[i].y), "=r"(fah[i].z), "=r"(fah[i].w) : "r"(ad));
        asm volatile("ldmatrix.sync.aligned.m8n8.x4.shared.b16 {%0,%1,%2,%3}, [%4];"
          : "=r"(fal[i].x), "=r"(fal[i].y), "=r"(fal[i].z), "=r"(fal[i].w) : "r"(ad + OFF_AL));
      }
      uint2 fwh[6], fwl[6];
      int kl = ks*16 + (lane & 15);
      #pragma unroll
      for (int j = 0; j < 6; j++) {
        uint32_t wd = st + OFF_WH + (uint32_t)kl*W_PAD + (uint32_t)(warpN*48 + j*8)*2;
        asm volatile("ldmatrix.sync.aligned.m8n8.x2.trans.shared.b16 {%0,%1}, [%2];"
          : "=r"(fwh[j].x), "=r"(fwh[j].y) : "r"(wd));
        asm volatile("ldmatrix.sync.aligned.m8n8.x2.trans.shared.b16 {%0,%1}, [%2];"
          : "=r"(fwl[j].x), "=r"(fwl[j].y) : "r"(wd + (OFF_WL - OFF_WH)));
      }
      #pragma unroll
      for (int i = 0; i < 2; i++)
        #pragma unroll
        for (int j = 0; j < 6; j++) MMA16816(acc[i][j], fah[i], fwh[j]);
      #pragma unroll
      for (int i = 0; i < 2; i++)
        #pragma unroll
        for (int j = 0; j < 6; j++) MMA16816(acc[i][j], fal[i], fwh[j]);
      #pragma unroll
      for (int i = 0; i < 2; i++)
        #pragma unroll
        for (int j = 0; j < 6; j++) MMA16816(acc[i][j], fah[i], fwl[j]);
    }
  }

  // epilogue: bias + gelu -> g_f
  int g = lane >> 2, q = lane & 3;
  #pragma unroll
  for (int i = 0; i < 2; i++) {
    int m = warpM*32 + i*16 + g;
    #pragma unroll
    for (int j = 0; j < 6; j++) {
      int n = n0 + warpN*48 + j*8 + q*2;
      float b0 = bias[n], b1 = bias[n+1];
      float2 r0, r1;
      r0.x = gelu_f(acc[i][j][0] + b0);
      r0.y = gelu_f(acc[i][j][1] + b1);
      r1.x = gelu_f(acc[i][j][2] + b0);
      r1.y = gelu_f(acc[i][j][3] + b1);
      *(float2*)(g_f + (size_t)m*FLATc + n)       = r0;
      *(float2*)(g_f + (size_t)(m + 8)*FLATc + n) = r1;
    }
  }
}

// ---------------- LN over FLAT -----------------------------------------------
__global__ void k_ln_flat(const float* __restrict__ ls, const float* __restrict__ lo) {
  int b = blockIdx.x; int t = threadIdx.x;
  float* frow = g_f + (size_t)b*FLATc;
  float s1 = 0.f, s2 = 0.f;
  for (int k = t; k < FLATc; k += 256) { float v = frow[k]; s1 += v; s2 += v*v; }
  blk_reduce2(s1, s2);
  float mu = s1 * (1.f/FLATc);
  float var = s2 * (1.f/FLATc) - mu*mu;
  float rs = rsqrtf(var + 1e-5f);
  for (int k = t; k < FLATc; k += 256) {
    float v = frow[k];
    frow[k] = (v - mu) * rs * ls[k] + lo[k];
  }
}

// ---------------- final out GEMM ---------------------------------------------
__global__ void k_out(const float* __restrict__ ow, const float* __restrict__ ob,
                      float* __restrict__ out) {
  int o = blockIdx.x, b = blockIdx.y;
  int t = threadIdx.x;
  const float* frow = g_f + (size_t)b*FLATc;
  float s1 = 0.f, s2 = 0.f;
  for (int k = t; k < FLATc; k += 256) s1 = fmaf(frow[k], ow[(size_t)k*HORc + o], s1);
  blk_reduce2(s1, s2);
  if (t == 0) out[b*HORc + o] = s1 + ob[o];
}

// ---------------- launch ------------------------------------------------------
extern "C" void kernel_launch(void* const* d_in, const int* in_sizes, int n_in,
                              void* d_out, int out_size) {
  const float* x      = (const float*)d_in[0];
  const float* proj_w = (const float*)d_in[1];
  const float* proj_b = (const float*)d_in[2];
  const float* ln0_s  = (const float*)d_in[3];
  const float* ln0_o  = (const float*)d_in[4];
  const float* conv_w = (const float*)d_in[5];
  const float* conv_b = (const float*)d_in[6];
  const float* ln1_s  = (const float*)d_in[7];
  const float* ln1_o  = (const float*)d_in[8];
  const float* qk_w   = (const float*)d_in[9];
  const float* qk_b   = (const float*)d_in[10];
  const float* mass_w = (const float*)d_in[11];
  const float* mass_b = (const float*)d_in[12];
  const float* v_w    = (const float*)d_in[13];
  const float* v_b    = (const float*)d_in[14];
  const float* norm_s = (const float*)d_in[15];
  const float* norm_o = (const float*)d_in[16];
  const float* mlp_w1 = (const float*)d_in[17];
  const float* mlp_b1 = (const float*)d_in[18];
  const float* mlp_w2 = (const float*)d_in[19];
  const float* mlp_b2 = (const float*)d_in[20];
  const float* fc_w   = (const float*)d_in[21];
  const float* fc_b   = (const float*)d_in[22];
  const float* ln2_s  = (const float*)d_in[23];
  const float* ln2_o  = (const float*)d_in[24];
  const float* out_w  = (const float*)d_in[25];
  const float* out_b  = (const float*)d_in[26];

  float *p_h, *p_qk, *p_v, *p_mlp;
  cudaGetSymbolAddress((void**)&p_h,   g_h);
  cudaGetSymbolAddress((void**)&p_qk,  g_qk);
  cudaGetSymbolAddress((void**)&p_v,   g_v);
  cudaGetSymbolAddress((void**)&p_mlp, g_mlp);

  cudaFuncSetAttribute(k_fc_mma, cudaFuncAttributeMaxDynamicSharedMemorySize, FC_SMEM);

  // W pre-conversion first (independent of everything else)
  k_convW<<<(FLATc*FLATc)/1024, 256>>>(fc_w);

  k_proj<<<ROWS, Ec>>>(x, proj_w, proj_b, ln0_s, ln0_o);
  k_conv<<<dim3(4, Bc), E2c>>>(conv_w);
  k_ln_gelu_conv<<<ROWS, E2c>>>(conv_b, ln1_s, ln1_o);

  for (int l = 0; l < Lc; l++) {
    k_gemm<<<dim3(E2c/BN, ROWS/BM), 256>>>(p_h, qk_w + (size_t)l*E2c*E2c,
                                           qk_b + l*E2c, nullptr, p_qk,
                                           ROWS, E2c, E2c, 0);
    k_gemm<<<dim3(E2c/BN, ROWS/BM), 256>>>(p_h, v_w + (size_t)l*E2c*E2c,
                                           v_b + l*E2c, nullptr, p_v,
                                           ROWS, E2c, E2c, 0);
    k_mass<<<ROWS/32, 256>>>(mass_w + (size_t)l*E2c*Hc, mass_b + l*Hc);
    k_attn<<<Bc*Hc, Sc>>>();
    k_res_ln_gelu<<<ROWS, E2c>>>(norm_s + l*E2c, norm_o + l*E2c);
  }

  k_gemm<<<dim3(MLPH/BN, ROWS/BM), 256>>>(p_h, mlp_w1, mlp_b1, nullptr, p_mlp,
                                          ROWS, MLPH, E2c, 1);
  k_gemm<<<dim3(E2c/BN, ROWS/BM), 256>>>(p_mlp, mlp_w2, mlp_b2, p_h, p_h,
                                         ROWS, E2c, MLPH, 0);

  k_split<<<(Bc*FLATc)/256, 256>>>();
  k_fc_mma<<<FLATc/FC_BN, 256, FC_SMEM>>>(fc_b);
  k_ln_flat<<<Bc, 256>>>(ln2_s, ln2_o);
  k_out<<<dim3(HORc, Bc), 256>>>(out_w, out_b, (float*)d_out);
}

// round 5
// speedup vs baseline: 1.6030x; 1.0732x over previous
#include <cuda_runtime.h>
#include <cuda_bf16.h>
#include <math.h>
#include <stdint.h>

#define Bc 128
#define Sc 64
#define FIN 32
#define Ec 96
#define E2c 192
#define Hc 8
#define Dc 24
#define Lc 4
#define HORc 24
#define FLATc (Sc*E2c)          // 12288
#define ROWS (Bc*Sc)            // 8192
#define MLPH (4*Ec)             // 384

// ---------------- scratch (static device globals; no allocation) ----------
__device__ float g_h0[ROWS*Ec];
__device__ float g_conv[ROWS*E2c];
__device__ float g_h[ROWS*E2c];
__device__ float g_qk[ROWS*E2c];
__device__ float g_v[ROWS*E2c];
__device__ float g_mass[Bc*Hc*Sc];
__device__ float g_att[ROWS*E2c];
__device__ float g_mlp[ROWS*MLPH];
__device__ float g_f[Bc*FLATc];
__device__ __nv_bfloat16 g_Ah[Bc*FLATc];        // fc activations hi
__device__ __nv_bfloat16 g_Al[Bc*FLATc];        // fc activations lo

// ---------------- helpers ---------------------------------------------------
__device__ __forceinline__ uint32_t smem_u32(const void* p) {
  uint32_t a;
  asm("{ .reg .u64 t; cvta.to.shared.u64 t, %1; cvt.u32.u64 %0, t; }" : "=r"(a) : "l"(p));
  return a;
}
__device__ __forceinline__ float gelu_f(float x) {
  float t = tanhf(0.7978845608028654f * (x + 0.044715f * x * x * x));
  return 0.5f * x * (1.f + t);
}
__device__ __forceinline__ float softplus_f(float x) {
  return fmaxf(x, 0.f) + log1pf(expf(-fabsf(x)));
}
__device__ __forceinline__ void blk_reduce2(float& a, float& b) {
  __shared__ float ra[256], rb[256];
  int t = threadIdx.x, n = blockDim.x;
  ra[t] = a; rb[t] = b;
  __syncthreads();
  #pragma unroll
  for (int s = 128; s > 0; s >>= 1) {
    if (t < s && t + s < n) { ra[t] += ra[t+s]; rb[t] += rb[t+s]; }
    __syncthreads();
  }
  a = ra[0]; b = rb[0];
}
__device__ __forceinline__ void split2(float a, float b, uint32_t& ph, uint32_t& pl) {
  __nv_bfloat16 ha = __float2bfloat16(a), hb = __float2bfloat16(b);
  float ra = a - __bfloat162float(ha), rb = b - __bfloat162float(hb);
  ph = ((uint32_t)__bfloat16_as_ushort(hb) << 16) | __bfloat16_as_ushort(ha);
  pl = ((uint32_t)__bfloat16_as_ushort(__float2bfloat16(rb)) << 16)
       | __bfloat16_as_ushort(__float2bfloat16(ra));
}

// ---------------- stage 1: proj -> LN -> gelu -------------------------------
__global__ void k_proj(const float* __restrict__ x, const float* __restrict__ w,
                       const float* __restrict__ bias, const float* __restrict__ ls,
                       const float* __restrict__ lo) {
  int row = blockIdx.x;
  int e = threadIdx.x;
  __shared__ float xs[FIN];
  if (e < FIN) xs[e] = x[row*FIN + e];
  __syncthreads();
  float acc = bias[e];
  #pragma unroll
  for (int k = 0; k < FIN; k++) acc = fmaf(xs[k], w[k*Ec + e], acc);
  float s1 = acc, s2 = acc*acc;
  blk_reduce2(s1, s2);
  float mu = s1 * (1.f/Ec);
  float var = s2 * (1.f/Ec) - mu*mu;
  float y = (acc - mu) * rsqrtf(var + 1e-5f) * ls[e] + lo[e];
  g_h0[row*Ec + e] = gelu_f(y);
}

// ---------------- stage 2: 4x4 SAME conv ------------------------------------
__global__ void k_conv(const float* __restrict__ cw) {
  int i  = blockIdx.y;
  int j0 = blockIdx.x * 16;
  int oc = threadIdx.x;
  __shared__ float sp[4][19*Ec];
  for (int idx = oc; idx < 4*19*Ec; idx += E2c) {
    int di  = idx / (19*Ec);
    int rem = idx - di*19*Ec;
    int col = rem / Ec;
    int c   = rem - col*Ec;
    int gi = i - 1 + di;
    int gj = j0 - 1 + col;
    float v = 0.f;
    if (gi >= 0 && gi < Bc && gj >= 0 && gj < Sc)
      v = g_h0[(gi*Sc + gj)*Ec + c];
    sp[di][col*Ec + c] = v;
  }
  __syncthreads();
  float acc[16];
  #pragma unroll
  for (int j = 0; j < 16; j++) acc[j] = 0.f;
  for (int di = 0; di < 4; di++) {
    for (int c = 0; c < Ec; c++) {
      float pv[19];
      #pragma unroll
      for (int t = 0; t < 19; t++) pv[t] = sp[di][t*Ec + c];
      #pragma unroll
      for (int dj = 0; dj < 4; dj++) {
        float wv = cw[((di*4 + dj)*Ec + c)*E2c + oc];
        #pragma unroll
        for (int j = 0; j < 16; j++) acc[j] = fmaf(pv[j + dj], wv, acc[j]);
      }
    }
  }
  #pragma unroll
  for (int j = 0; j < 16; j++)
    g_conv[(i*Sc + j0 + j)*E2c + oc] = acc[j];
}

// ---------------- stage 3: conv bias -> LN -> gelu --------------------------
__global__ void k_ln_gelu_conv(const float* __restrict__ cb,
                               const float* __restrict__ ls, const float* __restrict__ lo) {
  int row = blockIdx.x; int e = threadIdx.x;
  float v = g_conv[row*E2c + e] + cb[e];
  float s1 = v, s2 = v*v;
  blk_reduce2(s1, s2);
  float mu = s1 * (1.f/E2c);
  float var = s2 * (1.f/E2c) - mu*mu;
  g_h[row*E2c + e] = gelu_f((v - mu) * rsqrtf(var + 1e-5f) * ls[e] + lo[e]);
}

// ---------------- generic fp32 SIMT GEMM (small mats) ------------------------
#define BM 64
#define BN 64
#define BK 16
__global__ void k_gemm(const float* __restrict__ A, const float* __restrict__ W,
                       const float* __restrict__ bias, const float* res,
                       float* C, int M, int N, int K, int act) {
  __shared__ float As[BK][BM+1];
  __shared__ float Bs[BK][BN];
  int bn = blockIdx.x * BN, bm = blockIdx.y * BM;
  int tid = threadIdx.x;
  int tx = tid & 15, ty = tid >> 4;
  float acc[4][4];
  #pragma unroll
  for (int i = 0; i < 4; i++)
    #pragma unroll
    for (int j = 0; j < 4; j++) acc[i][j] = 0.f;
  for (int k0 = 0; k0 < K; k0 += BK) {
    #pragma unroll
    for (int i = 0; i < 4; i++) {
      int idx = tid + i*256;
      int m = idx >> 4, kk = idx & 15;
      As[kk][m] = A[(bm + m)*K + k0 + kk];
    }
    #pragma unroll
    for (int i = 0; i < 4; i++) {
      int idx = tid + i*256;
      int kk = idx >> 6, n = idx & 63;
      Bs[kk][n] = W[(k0 + kk)*N + bn + n];
    }
    __syncthreads();
    #pragma unroll
    for (int kk = 0; kk < BK; kk++) {
      float a[4], bb[4];
      #pragma unroll
      for (int i = 0; i < 4; i++) a[i] = As[kk][ty*4 + i];
      #pragma unroll
      for (int j = 0; j < 4; j++) bb[j] = Bs[kk][tx*4 + j];
      #pragma unroll
      for (int i = 0; i < 4; i++)
        #pragma unroll
        for (int j = 0; j < 4; j++) acc[i][j] = fmaf(a[i], bb[j], acc[i][j]);
    }
    __syncthreads();
  }
  #pragma unroll
  for (int i = 0; i < 4; i++) {
    int m = bm + ty*4 + i;
    #pragma unroll
    for (int j = 0; j < 4; j++) {
      int n = bn + tx*4 + j;
      float c = acc[i][j] + bias[n];
      if (act == 1) c = gelu_f(c);
      if (res) c += res[(size_t)m*N + n];
      C[(size_t)m*N + n] = c;
    }
  }
}

// ---------------- mass head --------------------------------------------------
__global__ void k_mass(const float* __restrict__ mw, const float* __restrict__ mb) {
  __shared__ float hs[32][E2c+1];
  __shared__ float ws[E2c*Hc];
  int r0 = blockIdx.x * 32;
  int tid = threadIdx.x;
  for (int idx = tid; idx < 32*E2c; idx += 256) {
    int r = idx / E2c, k = idx - (idx / E2c)*E2c;
    hs[r][k] = g_h[(r0 + r)*E2c + k];
  }
  for (int idx = tid; idx < E2c*Hc; idx += 256) ws[idx] = mw[idx];
  __syncthreads();
  int r = tid >> 3, hh = tid & 7;
  float acc = mb[hh];
  #pragma unroll 4
  for (int k = 0; k < E2c; k++) acc = fmaf(hs[r][k], ws[k*Hc + hh], acc);
  int row = r0 + r; int b = row >> 6, s = row & 63;
  g_mass[(b*Hc + hh)*Sc + s] = softplus_f(acc);
}

// ---------------- gravity attention core -------------------------------------
__global__ void k_attn() {
  int bh = blockIdx.x; int b = bh >> 3, hh = bh & 7;
  int i = threadIdx.x;
  __shared__ float qs[Sc][Dc+1];
  __shared__ float vs[Sc][Dc+1];
  __shared__ float ms[Sc];
  __shared__ float sq[Sc];
  const float* qbase = g_qk + (size_t)(b*Sc)*E2c + hh*Dc;
  const float* vbase = g_v  + (size_t)(b*Sc)*E2c + hh*Dc;
  float qi[Dc];
  float ssq = 0.f;
  #pragma unroll
  for (int d = 0; d < Dc; d++) {
    float q = qbase[i*E2c + d];
    qs[i][d] = q; qi[d] = q; ssq = fmaf(q, q, ssq);
    vs[i][d] = vbase[i*E2c + d];
  }
  sq[i] = ssq;
  ms[i] = g_mass[(b*Hc + hh)*Sc + i];
  __syncthreads();
  float mi = ms[i];
  float mmax = -INFINITY, l = 0.f;
  float acc[Dc];
  #pragma unroll
  for (int d = 0; d < Dc; d++) acc[d] = 0.f;
  for (int j = 0; j < Sc; j++) {
    float dot = 0.f;
    #pragma unroll
    for (int d = 0; d < Dc; d++) dot = fmaf(qi[d], qs[j][d], dot);
    float d2 = fmaxf(ssq + sq[j] - 2.f*dot, 0.f) + 1e-6f;
    float sc = mi * ms[j] / d2;
    float mn = fmaxf(mmax, sc);
    float scale = __expf(mmax - mn);
    float p = __expf(sc - mn);
    l = l*scale + p;
    #pragma unroll
    for (int d = 0; d < Dc; d++) acc[d] = fmaf(p, vs[j][d], acc[d]*scale);
    mmax = mn;
  }
  float inv = 1.f / l;
  float* obase = g_att + (size_t)(b*Sc + i)*E2c + hh*Dc;
  #pragma unroll
  for (int d = 0; d < Dc; d++) obase[d] = acc[d] * inv;
}

// ---------------- residual + LN + gelu ---------------------------------------
__global__ void k_res_ln_gelu(const float* __restrict__ ls, const float* __restrict__ lo) {
  int row = blockIdx.x; int e = threadIdx.x;
  float v = g_h[row*E2c + e] + g_att[row*E2c + e];
  float s1 = v, s2 = v*v;
  blk_reduce2(s1, s2);
  float mu = s1 * (1.f/E2c);
  float var = s2 * (1.f/E2c) - mu*mu;
  g_h[row*E2c + e] = gelu_f((v - mu) * rsqrtf(var + 1e-5f) * ls[e] + lo[e]);
}

// ---------------- fc activation hi/lo split ----------------------------------
__global__ void k_split() {
  int i = blockIdx.x * 256 + threadIdx.x;
  float v = g_h[i];
  __nv_bfloat16 hi = __float2bfloat16(v);
  __nv_bfloat16 lo = __float2bfloat16(v - __bfloat162float(hi));
  g_Ah[i] = hi;
  g_Al[i] = lo;
}

// ---------------- fc GEMM: cp.async fp32-W + in-loop convert + bf16 mma ------
// D[128, 96-slab] = A[128,12288] @ W[12288,12288]; 3-product hi/lo compensation.
// grid=128 CTAs, 256 thr (8 warps = 4m x 2n), warp tile 32m x 48n.
// Stages hold raw fp32 W; converted Wh/Wl bf16 tiles are double-buffered.
#define FC_BN 96
#define FC_BK 32
#define FC_IT (FLATc/FC_BK)     // 384
#define FC_ST 4
#define A_PAD 80                // 4x16B chunks padded to 5 -> conflict-free LDSM
#define W_PAD 208               // 12x16B chunks padded to 13 -> conflict-free LDSM
#define OFF_AL 10240            // 128*80
#define OFF_W32 20480           // fp32 W tile, 32 rows x 384B
#define ST_SZ  32768            // 10240+10240+12288
#define CV_OFF (FC_ST*ST_SZ)    // 131072
#define CV_BUF 13312            // Wh(32*208) + Wl(32*208)
#define FC_SMEM (CV_OFF + 2*CV_BUF)   // 157696

#define MMA16816(d, a, b) \
  asm volatile("mma.sync.aligned.m16n8k16.row.col.f32.bf16.bf16.f32 " \
    "{%0,%1,%2,%3}, {%4,%5,%6,%7}, {%8,%9}, {%0,%1,%2,%3};" \
    : "+f"((d)[0]), "+f"((d)[1]), "+f"((d)[2]), "+f"((d)[3]) \
    : "r"((a).x), "r"((a).y), "r"((a).z), "r"((a).w), "r"((b).x), "r"((b).y))

__device__ __forceinline__ void cp16(uint32_t d, const void* s) {
  asm volatile("cp.async.cg.shared.global [%0], [%1], 16;" :: "r"(d), "l"(s));
}

__device__ __forceinline__ void fc_stage_load(uint32_t sb, int slot, int k0, int n0,
                                              const float* __restrict__ W, int tid) {
  uint32_t st = sb + slot*ST_SZ;
  // A hi/lo: 512 16B-chunks each (128 rows x 4 chunks)
  {
    int g0 = tid * 2;
    #pragma unroll
    for (int t = 0; t < 2; t++) {
      int g = g0 + t;
      int m = g >> 2, c = g & 3;
      uint32_t d = st + m*A_PAD + c*16;
      size_t src = (size_t)m*FLATc + k0 + c*8;
      cp16(d, g_Ah + src);
      cp16(d + OFF_AL, g_Al + src);
    }
  }
  // W fp32: 32 k-rows x 96 n = 12288B = 768 chunks; 3 per thread
  #pragma unroll
  for (int t = 0; t < 3; t++) {
    int g = tid + t*256;
    int k = g / 24, c = g - k*24;
    uint32_t d = st + OFF_W32 + k*384 + c*16;
    cp16(d, W + (size_t)(k0 + k)*FLATc + n0 + c*4);
  }
}

__global__ void __launch_bounds__(256, 1) k_fc_mma(const float* __restrict__ W,
                                                   const float* __restrict__ bias) {
  extern __shared__ char smc[];
  uint32_t sb = smem_u32(smc);
  int tid = threadIdx.x, lane = tid & 31, wp = tid >> 5;
  int warpM = wp >> 1, warpN = wp & 1;
  int n0 = blockIdx.x * FC_BN;

  float acc[2][6][4];
  #pragma unroll
  for (int i = 0; i < 2; i++)
    #pragma unroll
    for (int j = 0; j < 6; j++)
      #pragma unroll
      for (int c = 0; c < 4; c++) acc[i][j][c] = 0.f;

  #pragma unroll
  for (int s = 0; s < FC_ST - 1; s++) {
    fc_stage_load(sb, s, s*FC_BK, n0, W, tid);
    asm volatile("cp.async.commit_group;" ::: "memory");
  }

  int arow = warpM*32 + (lane & 15);
  // convert mapping: krow = tid>>3, n-segment of 12 floats
  int ckrow = tid >> 3, cseg = tid & 7;

  for (int it = 0; it < FC_IT; it++) {
    asm volatile("cp.async.wait_group 2;" ::: "memory");
    __syncthreads();

    // ---- convert fp32 W tile (stage it) -> bf16 hi/lo conv buffer (it&1) ----
    {
      uint32_t src = sb + (it & 3)*ST_SZ + OFF_W32 + (uint32_t)ckrow*384 + cseg*48;
      uint32_t dh  = sb + CV_OFF + (it & 1)*CV_BUF + (uint32_t)ckrow*W_PAD + cseg*24;
      float4 f0, f1, f2;
      asm volatile("ld.shared.v4.f32 {%0,%1,%2,%3}, [%4];"
        : "=f"(f0.x), "=f"(f0.y), "=f"(f0.z), "=f"(f0.w) : "r"(src));
      asm volatile("ld.shared.v4.f32 {%0,%1,%2,%3}, [%4];"
        : "=f"(f1.x), "=f"(f1.y), "=f"(f1.z), "=f"(f1.w) : "r"(src + 16));
      asm volatile("ld.shared.v4.f32 {%0,%1,%2,%3}, [%4];"
        : "=f"(f2.x), "=f"(f2.y), "=f"(f2.z), "=f"(f2.w) : "r"(src + 32));
      uint32_t h[6], l[6];
      split2(f0.x, f0.y, h[0], l[0]);
      split2(f0.z, f0.w, h[1], l[1]);
      split2(f1.x, f1.y, h[2], l[2]);
      split2(f1.z, f1.w, h[3], l[3]);
      split2(f2.x, f2.y, h[4], l[4]);
      split2(f2.z, f2.w, h[5], l[5]);
      asm volatile("st.shared.v2.b32 [%0], {%1,%2};" :: "r"(dh),      "r"(h[0]), "r"(h[1]));
      asm volatile("st.shared.v2.b32 [%0], {%1,%2};" :: "r"(dh + 8),  "r"(h[2]), "r"(h[3]));
      asm volatile("st.shared.v2.b32 [%0], {%1,%2};" :: "r"(dh + 16), "r"(h[4]), "r"(h[5]));
      uint32_t dl = dh + 6656;
      asm volatile("st.shared.v2.b32 [%0], {%1,%2};" :: "r"(dl),      "r"(l[0]), "r"(l[1]));
      asm volatile("st.shared.v2.b32 [%0], {%1,%2};" :: "r"(dl + 8),  "r"(l[2]), "r"(l[3]));
      asm volatile("st.shared.v2.b32 [%0], {%1,%2};" :: "r"(dl + 16), "r"(l[4]), "r"(l[5]));
    }
    __syncthreads();

    // ---- issue next stage load ----
    if (it + FC_ST - 1 < FC_IT) {
      fc_stage_load(sb, (it + FC_ST - 1) & 3, (it + FC_ST - 1)*FC_BK, n0, W, tid);
    }
    asm volatile("cp.async.commit_group;" ::: "memory");

    // ---- compute ----
    uint32_t st = sb + (it & 3)*ST_SZ;
    uint32_t cv = sb + CV_OFF + (it & 1)*CV_BUF;
    #pragma unroll
    for (int ks = 0; ks < 2; ks++) {
      uint4 fah[2], fal[2];
      int c = ks*2 + (lane >> 4);
      #pragma unroll
      for (int i = 0; i < 2; i++) {
        uint32_t ad = st + (uint32_t)(arow + i*16)*A_PAD + c*16;
        asm volatile("ldmatrix.sync.aligned.m8n8.x4.shared.b16 {%0,%1,%2,%3}, [%4];"
          : "=r"(fah[i].x), "=r"(fah[i].y), "=r"(fah[i].z), "=r"(fah[i].w) : "r"(ad));
        asm volatile("ldmatrix.sync.aligned.m8n8.x4.shared.b16 {%0,%1,%2,%3}, [%4];"
          : "=r"(fal[i].x), "=r"(fal[i].y), "=r"(fal[i].z), "=r"(fal[i].w) : "r"(ad + OFF_AL));
      }
      uint2 fwh[6], fwl[6];
      int kl = ks*16 + (lane & 15);
      #pragma unroll
      for (int j = 0; j < 6; j++) {
        uint32_t wd = cv + (uint32_t)kl*W_PAD + (uint32_t)(warpN*48 + j*8)*2;
        asm volatile("ldmatrix.sync.aligned.m8n8.x2.trans.shared.b16 {%0,%1}, [%2];"
          : "=r"(fwh[j].x), "=r"(fwh[j].y) : "r"(wd));
        asm volatile("ldmatrix.sync.aligned.m8n8.x2.trans.shared.b16 {%0,%1}, [%2];"
          : "=r"(fwl[j].x), "=r"(fwl[j].y) : "r"(wd + 6656));
      }
      #pragma unroll
      for (int i = 0; i < 2; i++)
        #pragma unroll
        for (int j = 0; j < 6; j++) MMA16816(acc[i][j], fah[i], fwh[j]);
      #pragma unroll
      for (int i = 0; i < 2; i++)
        #pragma unroll
        for (int j = 0; j < 6; j++) MMA16816(acc[i][j], fal[i], fwh[j]);
      #pragma unroll
      for (int i = 0; i < 2; i++)
        #pragma unroll
        for (int j = 0; j < 6; j++) MMA16816(acc[i][j], fah[i], fwl[j]);
    }
  }

  // epilogue: bias + gelu -> g_f
  int g = lane >> 2, q = lane & 3;
  #pragma unroll
  for (int i = 0; i < 2; i++) {
    int m = warpM*32 + i*16 + g;
    #pragma unroll
    for (int j = 0; j < 6; j++) {
      int n = n0 + warpN*48 + j*8 + q*2;
      float b0 = bias[n], b1 = bias[n+1];
      float2 r0, r1;
      r0.x = gelu_f(acc[i][j][0] + b0);
      r0.y = gelu_f(acc[i][j][1] + b1);
      r1.x = gelu_f(acc[i][j][2] + b0);
      r1.y = gelu_f(acc[i][j][3] + b1);
      *(float2*)(g_f + (size_t)m*FLATc + n)       = r0;
      *(float2*)(g_f + (size_t)(m + 8)*FLATc + n) = r1;
    }
  }
}

// ---------------- LN over FLAT -----------------------------------------------
__global__ void k_ln_flat(const float* __restrict__ ls, const float* __restrict__ lo) {
  int b = blockIdx.x; int t = threadIdx.x;
  float* frow = g_f + (size_t)b*FLATc;
  float s1 = 0.f, s2 = 0.f;
  for (int k = t; k < FLATc; k += 256) { float v = frow[k]; s1 += v; s2 += v*v; }
  blk_reduce2(s1, s2);
  float mu = s1 * (1.f/FLATc);
  float var = s2 * (1.f/FLATc) - mu*mu;
  float rs = rsqrtf(var + 1e-5f);
  for (int k = t; k < FLATc; k += 256) {
    float v = frow[k];
    frow[k] = (v - mu) * rs * ls[k] + lo[k];
  }
}

// ---------------- final out GEMM ---------------------------------------------
__global__ void k_out(const float* __restrict__ ow, const float* __restrict__ ob,
                      float* __restrict__ out) {
  int o = blockIdx.x, b = blockIdx.y;
  int t = threadIdx.x;
  const float* frow = g_f + (size_t)b*FLATc;
  float s1 = 0.f, s2 = 0.f;
  for (int k = t; k < FLATc; k += 256) s1 = fmaf(frow[k], ow[(size_t)k*HORc + o], s1);
  blk_reduce2(s1, s2);
  if (t == 0) out[b*HORc + o] = s1 + ob[o];
}

// ---------------- launch ------------------------------------------------------
extern "C" void kernel_launch(void* const* d_in, const int* in_sizes, int n_in,
                              void* d_out, int out_size) {
  const float* x      = (const float*)d_in[0];
  const float* proj_w = (const float*)d_in[1];
  const float* proj_b = (const float*)d_in[2];
  const float* ln0_s  = (const float*)d_in[3];
  const float* ln0_o  = (const float*)d_in[4];
  const float* conv_w = (const float*)d_in[5];
  const float* conv_b = (const float*)d_in[6];
  const float* ln1_s  = (const float*)d_in[7];
  const float* ln1_o  = (const float*)d_in[8];
  const float* qk_w   = (const float*)d_in[9];
  const float* qk_b   = (const float*)d_in[10];
  const float* mass_w = (const float*)d_in[11];
  const float* mass_b = (const float*)d_in[12];
  const float* v_w    = (const float*)d_in[13];
  const float* v_b    = (const float*)d_in[14];
  const float* norm_s = (const float*)d_in[15];
  const float* norm_o = (const float*)d_in[16];
  const float* mlp_w1 = (const float*)d_in[17];
  const float* mlp_b1 = (const float*)d_in[18];
  const float* mlp_w2 = (const float*)d_in[19];
  const float* mlp_b2 = (const float*)d_in[20];
  const float* fc_w   = (const float*)d_in[21];
  const float* fc_b   = (const float*)d_in[22];
  const float* ln2_s  = (const float*)d_in[23];
  const float* ln2_o  = (const float*)d_in[24];
  const float* out_w  = (const float*)d_in[25];
  const float* out_b  = (const float*)d_in[26];

  float *p_h, *p_qk, *p_v, *p_mlp;
  cudaGetSymbolAddress((void**)&p_h,   g_h);
  cudaGetSymbolAddress((void**)&p_qk,  g_qk);
  cudaGetSymbolAddress((void**)&p_v,   g_v);
  cudaGetSymbolAddress((void**)&p_mlp, g_mlp);

  cudaFuncSetAttribute(k_fc_mma, cudaFuncAttributeMaxDynamicSharedMemorySize, FC_SMEM);

  k_proj<<<ROWS, Ec>>>(x, proj_w, proj_b, ln0_s, ln0_o);
  k_conv<<<dim3(4, Bc), E2c>>>(conv_w);
  k_ln_gelu_conv<<<ROWS, E2c>>>(conv_b, ln1_s, ln1_o);

  for (int l = 0; l < Lc; l++) {
    k_gemm<<<dim3(E2c/BN, ROWS/BM), 256>>>(p_h, qk_w + (size_t)l*E2c*E2c,
                                           qk_b + l*E2c, nullptr, p_qk,
                                           ROWS, E2c, E2c, 0);
    k_gemm<<<dim3(E2c/BN, ROWS/BM), 256>>>(p_h, v_w + (size_t)l*E2c*E2c,
                                           v_b + l*E2c, nullptr, p_v,
                                           ROWS, E2c, E2c, 0);
    k_mass<<<ROWS/32, 256>>>(mass_w + (size_t)l*E2c*Hc, mass_b + l*Hc);
    k_attn<<<Bc*Hc, Sc>>>();
    k_res_ln_gelu<<<ROWS, E2c>>>(norm_s + l*E2c, norm_o + l*E2c);
  }

  k_gemm<<<dim3(MLPH/BN, ROWS/BM), 256>>>(p_h, mlp_w1, mlp_b1, nullptr, p_mlp,
                                          ROWS, MLPH, E2c, 1);
  k_gemm<<<dim3(E2c/BN, ROWS/BM), 256>>>(p_mlp, mlp_w2, mlp_b2, p_h, p_h,
                                         ROWS, E2c, MLPH, 0);

  k_split<<<(Bc*FLATc)/256, 256>>>();
  k_fc_mma<<<FLATc/FC_BN, 256, FC_SMEM>>>(fc_w, fc_b);
  k_ln_flat<<<Bc, 256>>>(ln2_s, ln2_o);
  k_out<<<dim3(HORc, Bc), 256>>>(out_w, out_b, (float*)d_out);
}

// round 6
// speedup vs baseline: 1.7061x; 1.0643x over previous
#include <cuda_runtime.h>
#include <cuda_bf16.h>
#include <math.h>
#include <stdint.h>

#define Bc 128
#define Sc 64
#define FIN 32
#define Ec 96
#define E2c 192
#define Hc 8
#define Dc 24
#define Lc 4
#define HORc 24
#define FLATc (Sc*E2c)          // 12288
#define ROWS (Bc*Sc)            // 8192
#define MLPH (4*Ec)             // 384

// ---------------- scratch (static device globals; no allocation) ----------
__device__ float g_h0[ROWS*Ec];
__device__ float g_conv[ROWS*E2c];
__device__ float g_h[ROWS*E2c];
__device__ float g_qk[ROWS*E2c];
__device__ float g_v[ROWS*E2c];
__device__ float g_mass[Bc*Hc*Sc];
__device__ float g_att[ROWS*E2c];
__device__ float g_f[Bc*FLATc];
__device__ __nv_bfloat16 g_Ah[ROWS*E2c];        // hi/lo split of current activations
__device__ __nv_bfloat16 g_Al[ROWS*E2c];
__device__ __nv_bfloat16 g_Mh[ROWS*MLPH];       // mlp hidden (bf16 pair)
__device__ __nv_bfloat16 g_Ml[ROWS*MLPH];

// ---------------- helpers ---------------------------------------------------
__device__ __forceinline__ uint32_t smem_u32(const void* p) {
  uint32_t a;
  asm("{ .reg .u64 t; cvta.to.shared.u64 t, %1; cvt.u32.u64 %0, t; }" : "=r"(a) : "l"(p));
  return a;
}
__device__ __forceinline__ float gelu_f(float x) {
  float t = tanhf(0.7978845608028654f * (x + 0.044715f * x * x * x));
  return 0.5f * x * (1.f + t);
}
__device__ __forceinline__ float softplus_f(float x) {
  return fmaxf(x, 0.f) + log1pf(expf(-fabsf(x)));
}
__device__ __forceinline__ void blk_reduce2(float& a, float& b) {
  __shared__ float ra[256], rb[256];
  int t = threadIdx.x, n = blockDim.x;
  ra[t] = a; rb[t] = b;
  __syncthreads();
  #pragma unroll
  for (int s = 128; s > 0; s >>= 1) {
    if (t < s && t + s < n) { ra[t] += ra[t+s]; rb[t] += rb[t+s]; }
    __syncthreads();
  }
  a = ra[0]; b = rb[0];
}
__device__ __forceinline__ void split2(float a, float b, uint32_t& ph, uint32_t& pl) {
  __nv_bfloat16 ha = __float2bfloat16(a), hb = __float2bfloat16(b);
  float ra = a - __bfloat162float(ha), rb = b - __bfloat162float(hb);
  ph = ((uint32_t)__bfloat16_as_ushort(hb) << 16) | __bfloat16_as_ushort(ha);
  pl = ((uint32_t)__bfloat16_as_ushort(__float2bfloat16(rb)) << 16)
       | __bfloat16_as_ushort(__float2bfloat16(ra));
}
#define MMA16816(d, a, b) \
  asm volatile("mma.sync.aligned.m16n8k16.row.col.f32.bf16.bf16.f32 " \
    "{%0,%1,%2,%3}, {%4,%5,%6,%7}, {%8,%9}, {%0,%1,%2,%3};" \
    : "+f"((d)[0]), "+f"((d)[1]), "+f"((d)[2]), "+f"((d)[3]) \
    : "r"((a).x), "r"((a).y), "r"((a).z), "r"((a).w), "r"((b).x), "r"((b).y))
__device__ __forceinline__ void cp16(uint32_t d, const void* s) {
  asm volatile("cp.async.cg.shared.global [%0], [%1], 16;" :: "r"(d), "l"(s));
}

// ---------------- stage 1: proj -> LN -> gelu -------------------------------
__global__ void k_proj(const float* __restrict__ x, const float* __restrict__ w,
                       const float* __restrict__ bias, const float* __restrict__ ls,
                       const float* __restrict__ lo) {
  int row = blockIdx.x;
  int e = threadIdx.x;
  __shared__ float xs[FIN];
  if (e < FIN) xs[e] = x[row*FIN + e];
  __syncthreads();
  float acc = bias[e];
  #pragma unroll
  for (int k = 0; k < FIN; k++) acc = fmaf(xs[k], w[k*Ec + e], acc);
  float s1 = acc, s2 = acc*acc;
  blk_reduce2(s1, s2);
  float mu = s1 * (1.f/Ec);
  float var = s2 * (1.f/Ec) - mu*mu;
  float y = (acc - mu) * rsqrtf(var + 1e-5f) * ls[e] + lo[e];
  g_h0[row*Ec + e] = gelu_f(y);
}

// ---------------- stage 2: 4x4 SAME conv ------------------------------------
__global__ void k_conv(const float* __restrict__ cw) {
  int i  = blockIdx.y;
  int j0 = blockIdx.x * 16;
  int oc = threadIdx.x;
  __shared__ float sp[4][19*Ec];
  for (int idx = oc; idx < 4*19*Ec; idx += E2c) {
    int di  = idx / (19*Ec);
    int rem = idx - di*19*Ec;
    int col = rem / Ec;
    int c   = rem - col*Ec;
    int gi = i - 1 + di;
    int gj = j0 - 1 + col;
    float v = 0.f;
    if (gi >= 0 && gi < Bc && gj >= 0 && gj < Sc)
      v = g_h0[(gi*Sc + gj)*Ec + c];
    sp[di][col*Ec + c] = v;
  }
  __syncthreads();
  float acc[16];
  #pragma unroll
  for (int j = 0; j < 16; j++) acc[j] = 0.f;
  for (int di = 0; di < 4; di++) {
    for (int c = 0; c < Ec; c++) {
      float pv[19];
      #pragma unroll
      for (int t = 0; t < 19; t++) pv[t] = sp[di][t*Ec + c];
      #pragma unroll
      for (int dj = 0; dj < 4; dj++) {
        float wv = cw[((di*4 + dj)*Ec + c)*E2c + oc];
        #pragma unroll
        for (int j = 0; j < 16; j++) acc[j] = fmaf(pv[j + dj], wv, acc[j]);
      }
    }
  }
  #pragma unroll
  for (int j = 0; j < 16; j++)
    g_conv[(i*Sc + j0 + j)*E2c + oc] = acc[j];
}

// ---------------- stage 3: conv bias -> LN -> gelu --------------------------
__global__ void k_ln_gelu_conv(const float* __restrict__ cb,
                               const float* __restrict__ ls, const float* __restrict__ lo) {
  int row = blockIdx.x; int e = threadIdx.x;
  float v = g_conv[row*E2c + e] + cb[e];
  float s1 = v, s2 = v*v;
  blk_reduce2(s1, s2);
  float mu = s1 * (1.f/E2c);
  float var = s2 * (1.f/E2c) - mu*mu;
  g_h[row*E2c + e] = gelu_f((v - mu) * rsqrtf(var + 1e-5f) * ls[e] + lo[e]);
}

// ---------------- hi/lo split (vectorized) ----------------------------------
__global__ void k_split2(const float* __restrict__ src,
                         __nv_bfloat16* __restrict__ dh, __nv_bfloat16* __restrict__ dl) {
  size_t i = ((size_t)blockIdx.x * 256 + threadIdx.x) * 4;
  float4 v = *(const float4*)(src + i);
  uint2 ph, pl;
  split2(v.x, v.y, ph.x, pl.x);
  split2(v.z, v.w, ph.y, pl.y);
  *(uint2*)(dh + i) = ph;
  *(uint2*)(dl + i) = pl;
}

// ---------------- tensor-core small GEMM ------------------------------------
// C[8192, N-slab64] = A[8192,K] @ W[K,N]; bf16 hi/lo 3-product; 256 thr, 8 warps 4x2.
// mode 0: C = acc+bias    mode 1: Oh/Ol = split(gelu(acc+bias))    mode 2: C = acc+bias+res
#define GT_APAD 80
#define GT_OFFAL 10240
#define GT_OFFW 20480
#define GT_STSZ 28672
#define GT_CV 57344
#define GT_CVLO 4608
#define GT_WPAD 144
#define GT_SMEM 66560

__global__ void __launch_bounds__(256) k_gemm_tc(
    const __nv_bfloat16* __restrict__ Ah, const __nv_bfloat16* __restrict__ Al,
    const float* __restrict__ W, const float* __restrict__ bias,
    const float* __restrict__ res, float* __restrict__ C,
    __nv_bfloat16* __restrict__ Oh, __nv_bfloat16* __restrict__ Ol,
    int N, int K, int mode) {
  extern __shared__ char smc[];
  uint32_t sb = smem_u32(smc);
  int tid = threadIdx.x, lane = tid & 31, wp = tid >> 5;
  int warpM = wp >> 1, warpN = wp & 1;
  int n0 = blockIdx.x * 64, m0 = blockIdx.y * 128;
  int KIT = K >> 5;

  float acc[2][4][4];
  #pragma unroll
  for (int i = 0; i < 2; i++)
    #pragma unroll
    for (int j = 0; j < 4; j++)
      #pragma unroll
      for (int c = 0; c < 4; c++) acc[i][j][c] = 0.f;

  auto load_stage = [&](int slot, int k0) {
    uint32_t st = sb + slot*GT_STSZ;
    #pragma unroll
    for (int t = 0; t < 2; t++) {
      int g = tid*2 + t;
      int m = g >> 2, c = g & 3;
      uint32_t d = st + m*GT_APAD + c*16;
      size_t src = (size_t)(m0 + m)*K + k0 + c*8;
      cp16(d, Ah + src);
      cp16(d + GT_OFFAL, Al + src);
    }
    #pragma unroll
    for (int t = 0; t < 2; t++) {
      int g = tid*2 + t;
      int k = g >> 4, c = g & 15;
      cp16(st + GT_OFFW + k*256 + c*16, W + (size_t)(k0 + k)*N + n0 + c*4);
    }
  };

  load_stage(0, 0);
  asm volatile("cp.async.commit_group;" ::: "memory");

  int arow = warpM*32 + (lane & 15);
  int ckrow = tid >> 3, cseg = tid & 7;

  for (int it = 0; it < KIT; it++) {
    asm volatile("cp.async.wait_group 0;" ::: "memory");
    __syncthreads();
    if (it + 1 < KIT) load_stage((it + 1) & 1, (it + 1)*32);
    asm volatile("cp.async.commit_group;" ::: "memory");
    // convert fp32 W tile -> bf16 hi/lo CV
    {
      uint32_t src = sb + (it & 1)*GT_STSZ + GT_OFFW + (uint32_t)ckrow*256 + cseg*32;
      uint32_t dh  = sb + GT_CV + (uint32_t)ckrow*GT_WPAD + cseg*16;
      float4 f0, f1;
      asm volatile("ld.shared.v4.f32 {%0,%1,%2,%3}, [%4];"
        : "=f"(f0.x), "=f"(f0.y), "=f"(f0.z), "=f"(f0.w) : "r"(src));
      asm volatile("ld.shared.v4.f32 {%0,%1,%2,%3}, [%4];"
        : "=f"(f1.x), "=f"(f1.y), "=f"(f1.z), "=f"(f1.w) : "r"(src + 16));
      uint32_t h[4], l[4];
      split2(f0.x, f0.y, h[0], l[0]);
      split2(f0.z, f0.w, h[1], l[1]);
      split2(f1.x, f1.y, h[2], l[2]);
      split2(f1.z, f1.w, h[3], l[3]);
      asm volatile("st.shared.v4.b32 [%0], {%1,%2,%3,%4};"
        :: "r"(dh), "r"(h[0]), "r"(h[1]), "r"(h[2]), "r"(h[3]));
      asm volatile("st.shared.v4.b32 [%0], {%1,%2,%3,%4};"
        :: "r"(dh + GT_CVLO), "r"(l[0]), "r"(l[1]), "r"(l[2]), "r"(l[3]));
    }
    __syncthreads();
    // compute
    uint32_t st = sb + (it & 1)*GT_STSZ;
    uint32_t cv = sb + GT_CV;
    #pragma unroll
    for (int ks = 0; ks < 2; ks++) {
      uint4 fah[2], fal[2];
      int c = ks*2 + (lane >> 4);
      #pragma unroll
      for (int i = 0; i < 2; i++) {
        uint32_t ad = st + (uint32_t)(arow + i*16)*GT_APAD + c*16;
        asm volatile("ldmatrix.sync.aligned.m8n8.x4.shared.b16 {%0,%1,%2,%3}, [%4];"
          : "=r"(fah[i].x), "=r"(fah[i].y), "=r"(fah[i].z), "=r"(fah[i].w) : "r"(ad));
        asm volatile("ldmatrix.sync.aligned.m8n8.x4.shared.b16 {%0,%1,%2,%3}, [%4];"
          : "=r"(fal[i].x), "=r"(fal[i].y), "=r"(fal[i].z), "=r"(fal[i].w) : "r"(ad + GT_OFFAL));
      }
      uint2 fwh[4], fwl[4];
      int kl = ks*16 + (lane & 15);
      #pragma unroll
      for (int j = 0; j < 4; j++) {
        uint32_t wd = cv + (uint32_t)kl*GT_WPAD + (uint32_t)(warpN*32 + j*8)*2;
        asm volatile("ldmatrix.sync.aligned.m8n8.x2.trans.shared.b16 {%0,%1}, [%2];"
          : "=r"(fwh[j].x), "=r"(fwh[j].y) : "r"(wd));
        asm volatile("ldmatrix.sync.aligned.m8n8.x2.trans.shared.b16 {%0,%1}, [%2];"
          : "=r"(fwl[j].x), "=r"(fwl[j].y) : "r"(wd + GT_CVLO));
      }
      #pragma unroll
      for (int i = 0; i < 2; i++)
        #pragma unroll
        for (int j = 0; j < 4; j++) MMA16816(acc[i][j], fah[i], fwh[j]);
      #pragma unroll
      for (int i = 0; i < 2; i++)
        #pragma unroll
        for (int j = 0; j < 4; j++) MMA16816(acc[i][j], fal[i], fwh[j]);
      #pragma unroll
      for (int i = 0; i < 2; i++)
        #pragma unroll
        for (int j = 0; j < 4; j++) MMA16816(acc[i][j], fah[i], fwl[j]);
    }
  }

  // epilogue
  int g = lane >> 2, q = lane & 3;
  #pragma unroll
  for (int i = 0; i < 2; i++) {
    int m = m0 + warpM*32 + i*16 + g;
    #pragma unroll
    for (int j = 0; j < 4; j++) {
      int n = n0 + warpN*32 + j*8 + q*2;
      float b0 = bias[n], b1 = bias[n+1];
      float v00 = acc[i][j][0] + b0, v01 = acc[i][j][1] + b1;
      float v10 = acc[i][j][2] + b0, v11 = acc[i][j][3] + b1;
      if (mode == 1) {
        uint32_t ph0, pl0, ph1, pl1;
        split2(gelu_f(v00), gelu_f(v01), ph0, pl0);
        split2(gelu_f(v10), gelu_f(v11), ph1, pl1);
        *(uint32_t*)(Oh + (size_t)m*N + n)     = ph0;
        *(uint32_t*)(Ol + (size_t)m*N + n)     = pl0;
        *(uint32_t*)(Oh + (size_t)(m+8)*N + n) = ph1;
        *(uint32_t*)(Ol + (size_t)(m+8)*N + n) = pl1;
      } else {
        if (mode == 2) {
          float2 r0 = *(const float2*)(res + (size_t)m*N + n);
          float2 r1 = *(const float2*)(res + (size_t)(m+8)*N + n);
          v00 += r0.x; v01 += r0.y; v10 += r1.x; v11 += r1.y;
        }
        *(float2*)(C + (size_t)m*N + n)     = make_float2(v00, v01);
        *(float2*)(C + (size_t)(m+8)*N + n) = make_float2(v10, v11);
      }
    }
  }
}

// ---------------- mass head --------------------------------------------------
__global__ void k_mass(const float* __restrict__ mw, const float* __restrict__ mb) {
  __shared__ float hs[32][E2c+1];
  __shared__ float ws[E2c*Hc];
  int r0 = blockIdx.x * 32;
  int tid = threadIdx.x;
  for (int idx = tid; idx < 32*E2c; idx += 256) {
    int r = idx / E2c, k = idx - (idx / E2c)*E2c;
    hs[r][k] = g_h[(r0 + r)*E2c + k];
  }
  for (int idx = tid; idx < E2c*Hc; idx += 256) ws[idx] = mw[idx];
  __syncthreads();
  int r = tid >> 3, hh = tid & 7;
  float acc = mb[hh];
  #pragma unroll 4
  for (int k = 0; k < E2c; k++) acc = fmaf(hs[r][k], ws[k*Hc + hh], acc);
  int row = r0 + r; int b = row >> 6, s = row & 63;
  g_mass[(b*Hc + hh)*Sc + s] = softplus_f(acc);
}

// ---------------- gravity attention core -------------------------------------
__global__ void k_attn() {
  int bh = blockIdx.x; int b = bh >> 3, hh = bh & 7;
  int i = threadIdx.x;
  __shared__ float qs[Sc][Dc+1];
  __shared__ float vs[Sc][Dc+1];
  __shared__ float ms[Sc];
  __shared__ float sq[Sc];
  const float* qbase = g_qk + (size_t)(b*Sc)*E2c + hh*Dc;
  const float* vbase = g_v  + (size_t)(b*Sc)*E2c + hh*Dc;
  float qi[Dc];
  float ssq = 0.f;
  #pragma unroll
  for (int d = 0; d < Dc; d++) {
    float q = qbase[i*E2c + d];
    qs[i][d] = q; qi[d] = q; ssq = fmaf(q, q, ssq);
    vs[i][d] = vbase[i*E2c + d];
  }
  sq[i] = ssq;
  ms[i] = g_mass[(b*Hc + hh)*Sc + i];
  __syncthreads();
  float mi = ms[i];
  float mmax = -INFINITY, l = 0.f;
  float acc[Dc];
  #pragma unroll
  for (int d = 0; d < Dc; d++) acc[d] = 0.f;
  for (int j = 0; j < Sc; j++) {
    float dot = 0.f;
    #pragma unroll
    for (int d = 0; d < Dc; d++) dot = fmaf(qi[d], qs[j][d], dot);
    float d2 = fmaxf(ssq + sq[j] - 2.f*dot, 0.f) + 1e-6f;
    float sc = mi * ms[j] / d2;
    float mn = fmaxf(mmax, sc);
    float scale = __expf(mmax - mn);
    float p = __expf(sc - mn);
    l = l*scale + p;
    #pragma unroll
    for (int d = 0; d < Dc; d++) acc[d] = fmaf(p, vs[j][d], acc[d]*scale);
    mmax = mn;
  }
  float inv = 1.f / l;
  float* obase = g_att + (size_t)(b*Sc + i)*E2c + hh*Dc;
  #pragma unroll
  for (int d = 0; d < Dc; d++) obase[d] = acc[d] * inv;
}

// ---------------- residual + LN + gelu ---------------------------------------
__global__ void k_res_ln_gelu(const float* __restrict__ ls, const float* __restrict__ lo) {
  int row = blockIdx.x; int e = threadIdx.x;
  float v = g_h[row*E2c + e] + g_att[row*E2c + e];
  float s1 = v, s2 = v*v;
  blk_reduce2(s1, s2);
  float mu = s1 * (1.f/E2c);
  float var = s2 * (1.f/E2c) - mu*mu;
  g_h[row*E2c + e] = gelu_f((v - mu) * rsqrtf(var + 1e-5f) * ls[e] + lo[e]);
}

// ---------------- fc GEMM: cp.async fp32-W + in-loop convert + bf16 mma ------
#define FC_BN 96
#define FC_BK 32
#define FC_IT (FLATc/FC_BK)     // 384
#define FC_ST 4
#define A_PAD 80
#define W_PAD 208
#define OFF_AL 10240
#define OFF_W32 20480
#define ST_SZ  32768
#define CV_OFF (FC_ST*ST_SZ)
#define CV_BUF 13312
#define FC_SMEM (CV_OFF + 2*CV_BUF)

__device__ __forceinline__ void fc_stage_load(uint32_t sb, int slot, int k0, int n0,
                                              const float* __restrict__ W, int tid) {
  uint32_t st = sb + slot*ST_SZ;
  {
    int g0 = tid * 2;
    #pragma unroll
    for (int t = 0; t < 2; t++) {
      int g = g0 + t;
      int m = g >> 2, c = g & 3;
      uint32_t d = st + m*A_PAD + c*16;
      size_t src = (size_t)m*FLATc + k0 + c*8;
      cp16(d, g_Ah + src);
      cp16(d + OFF_AL, g_Al + src);
    }
  }
  #pragma unroll
  for (int t = 0; t < 3; t++) {
    int g = tid + t*256;
    int k = g / 24, c = g - k*24;
    uint32_t d = st + OFF_W32 + k*384 + c*16;
    cp16(d, W + (size_t)(k0 + k)*FLATc + n0 + c*4);
  }
}

__global__ void __launch_bounds__(256, 1) k_fc_mma(const float* __restrict__ W,
                                                   const float* __restrict__ bias) {
  extern __shared__ char smc[];
  uint32_t sb = smem_u32(smc);
  int tid = threadIdx.x, lane = tid & 31, wp = tid >> 5;
  int warpM = wp >> 1, warpN = wp & 1;
  int n0 = blockIdx.x * FC_BN;

  float acc[2][6][4];
  #pragma unroll
  for (int i = 0; i < 2; i++)
    #pragma unroll
    for (int j = 0; j < 6; j++)
      #pragma unroll
      for (int c = 0; c < 4; c++) acc[i][j][c] = 0.f;

  #pragma unroll
  for (int s = 0; s < FC_ST - 1; s++) {
    fc_stage_load(sb, s, s*FC_BK, n0, W, tid);
    asm volatile("cp.async.commit_group;" ::: "memory");
  }

  int arow = warpM*32 + (lane & 15);
  int ckrow = tid >> 3, cseg = tid & 7;

  for (int it = 0; it < FC_IT; it++) {
    asm volatile("cp.async.wait_group 2;" ::: "memory");
    __syncthreads();

    // issue next stage load first (stage (it+3)&3 is free: consumed at it-1)
    if (it + FC_ST - 1 < FC_IT) {
      fc_stage_load(sb, (it + FC_ST - 1) & 3, (it + FC_ST - 1)*FC_BK, n0, W, tid);
    }
    asm volatile("cp.async.commit_group;" ::: "memory");

    // convert fp32 W tile (stage it) -> bf16 hi/lo conv buffer (it&1)
    {
      uint32_t src = sb + (it & 3)*ST_SZ + OFF_W32 + (uint32_t)ckrow*384 + cseg*48;
      uint32_t dh  = sb + CV_OFF + (it & 1)*CV_BUF + (uint32_t)ckrow*W_PAD + cseg*24;
      float4 f0, f1, f2;
      asm volatile("ld.shared.v4.f32 {%0,%1,%2,%3}, [%4];"
        : "=f"(f0.x), "=f"(f0.y), "=f"(f0.z), "=f"(f0.w) : "r"(src));
      asm volatile("ld.shared.v4.f32 {%0,%1,%2,%3}, [%4];"
        : "=f"(f1.x), "=f"(f1.y), "=f"(f1.z), "=f"(f1.w) : "r"(src + 16));
      asm volatile("ld.shared.v4.f32 {%0,%1,%2,%3}, [%4];"
        : "=f"(f2.x), "=f"(f2.y), "=f"(f2.z), "=f"(f2.w) : "r"(src + 32));
      uint32_t h[6], l[6];
      split2(f0.x, f0.y, h[0], l[0]);
      split2(f0.z, f0.w, h[1], l[1]);
      split2(f1.x, f1.y, h[2], l[2]);
      split2(f1.z, f1.w, h[3], l[3]);
      split2(f2.x, f2.y, h[4], l[4]);
      split2(f2.z, f2.w, h[5], l[5]);
      asm volatile("st.shared.v2.b32 [%0], {%1,%2};" :: "r"(dh),      "r"(h[0]), "r"(h[1]));
      asm volatile("st.shared.v2.b32 [%0], {%1,%2};" :: "r"(dh + 8),  "r"(h[2]), "r"(h[3]));
      asm volatile("st.shared.v2.b32 [%0], {%1,%2};" :: "r"(dh + 16), "r"(h[4]), "r"(h[5]));
      uint32_t dl = dh + 6656;
      asm volatile("st.shared.v2.b32 [%0], {%1,%2};" :: "r"(dl),      "r"(l[0]), "r"(l[1]));
      asm volatile("st.shared.v2.b32 [%0], {%1,%2};" :: "r"(dl + 8),  "r"(l[2]), "r"(l[3]));
      asm volatile("st.shared.v2.b32 [%0], {%1,%2};" :: "r"(dl + 16), "r"(l[4]), "r"(l[5]));
    }
    __syncthreads();

    // compute
    uint32_t st = sb + (it & 3)*ST_SZ;
    uint32_t cv = sb + CV_OFF + (it & 1)*CV_BUF;
    #pragma unroll
    for (int ks = 0; ks < 2; ks++) {
      uint4 fah[2], fal[2];
      int c = ks*2 + (lane >> 4);
      #pragma unroll
      for (int i = 0; i < 2; i++) {
        uint32_t ad = st + (uint32_t)(arow + i*16)*A_PAD + c*16;
        asm volatile("ldmatrix.sync.aligned.m8n8.x4.shared.b16 {%0,%1,%2,%3}, [%4];"
          : "=r"(fah[i].x), "=r"(fah[i].y), "=r"(fah[i].z), "=r"(fah[i].w) : "r"(ad));
        asm volatile("ldmatrix.sync.aligned.m8n8.x4.shared.b16 {%0,%1,%2,%3}, [%4];"
          : "=r"(fal[i].x), "=r"(fal[i].y), "=r"(fal[i].z), "=r"(fal[i].w) : "r"(ad + OFF_AL));
      }
      uint2 fwh[6], fwl[6];
      int kl = ks*16 + (lane & 15);
      #pragma unroll
      for (int j = 0; j < 6; j++) {
        uint32_t wd = cv + (uint32_t)kl*W_PAD + (uint32_t)(warpN*48 + j*8)*2;
        asm volatile("ldmatrix.sync.aligned.m8n8.x2.trans.shared.b16 {%0,%1}, [%2];"
          : "=r"(fwh[j].x), "=r"(fwh[j].y) : "r"(wd));
        asm volatile("ldmatrix.sync.aligned.m8n8.x2.trans.shared.b16 {%0,%1}, [%2];"
          : "=r"(fwl[j].x), "=r"(fwl[j].y) : "r"(wd + 6656));
      }
      #pragma unroll
      for (int i = 0; i < 2; i++)
        #pragma unroll
        for (int j = 0; j < 6; j++) MMA16816(acc[i][j], fah[i], fwh[j]);
      #pragma unroll
      for (int i = 0; i < 2; i++)
        #pragma unroll
        for (int j = 0; j < 6; j++) MMA16816(acc[i][j], fal[i], fwh[j]);
      #pragma unroll
      for (int i = 0; i < 2; i++)
        #pragma unroll
        for (int j = 0; j < 6; j++) MMA16816(acc[i][j], fah[i], fwl[j]);
    }
  }

  // epilogue: bias + gelu -> g_f
  int g = lane >> 2, q = lane & 3;
  #pragma unroll
  for (int i = 0; i < 2; i++) {
    int m = warpM*32 + i*16 + g;
    #pragma unroll
    for (int j = 0; j < 6; j++) {
      int n = n0 + warpN*48 + j*8 + q*2;
      float b0 = bias[n], b1 = bias[n+1];
      float2 r0, r1;
      r0.x = gelu_f(acc[i][j][0] + b0);
      r0.y = gelu_f(acc[i][j][1] + b1);
      r1.x = gelu_f(acc[i][j][2] + b0);
      r1.y = gelu_f(acc[i][j][3] + b1);
      *(float2*)(g_f + (size_t)m*FLATc + n)       = r0;
      *(float2*)(g_f + (size_t)(m + 8)*FLATc + n) = r1;
    }
  }
}

// ---------------- LN over FLAT -----------------------------------------------
__global__ void k_ln_flat(const float* __restrict__ ls, const float* __restrict__ lo) {
  int b = blockIdx.x; int t = threadIdx.x;
  float* frow = g_f + (size_t)b*FLATc;
  float s1 = 0.f, s2 = 0.f;
  for (int k = t; k < FLATc; k += 256) { float v = frow[k]; s1 += v; s2 += v*v; }
  blk_reduce2(s1, s2);
  float mu = s1 * (1.f/FLATc);
  float var = s2 * (1.f/FLATc) - mu*mu;
  float rs = rsqrtf(var + 1e-5f);
  for (int k = t; k < FLATc; k += 256) {
    float v = frow[k];
    frow[k] = (v - mu) * rs * ls[k] + lo[k];
  }
}

// ---------------- final out GEMM ---------------------------------------------
__global__ void k_out(const float* __restrict__ ow, const float* __restrict__ ob,
                      float* __restrict__ out) {
  int o = blockIdx.x, b = blockIdx.y;
  int t = threadIdx.x;
  const float* frow = g_f + (size_t)b*FLATc;
  float s1 = 0.f, s2 = 0.f;
  for (int k = t; k < FLATc; k += 256) s1 = fmaf(frow[k], ow[(size_t)k*HORc + o], s1);
  blk_reduce2(s1, s2);
  if (t == 0) out[b*HORc + o] = s1 + ob[o];
}

// ---------------- launch ------------------------------------------------------
extern "C" void kernel_launch(void* const* d_in, const int* in_sizes, int n_in,
                              void* d_out, int out_size) {
  const float* x      = (const float*)d_in[0];
  const float* proj_w = (const float*)d_in[1];
  const float* proj_b = (const float*)d_in[2];
  const float* ln0_s  = (const float*)d_in[3];
  const float* ln0_o  = (const float*)d_in[4];
  const float* conv_w = (const float*)d_in[5];
  const float* conv_b = (const float*)d_in[6];
  const float* ln1_s  = (const float*)d_in[7];
  const float* ln1_o  = (const float*)d_in[8];
  const float* qk_w   = (const float*)d_in[9];
  const float* qk_b   = (const float*)d_in[10];
  const float* mass_w = (const float*)d_in[11];
  const float* mass_b = (const float*)d_in[12];
  const float* v_w    = (const float*)d_in[13];
  const float* v_b    = (const float*)d_in[14];
  const float* norm_s = (const float*)d_in[15];
  const float* norm_o = (const float*)d_in[16];
  const float* mlp_w1 = (const float*)d_in[17];
  const float* mlp_b1 = (const float*)d_in[18];
  const float* mlp_w2 = (const float*)d_in[19];
  const float* mlp_b2 = (const float*)d_in[20];
  const float* fc_w   = (const float*)d_in[21];
  const float* fc_b   = (const float*)d_in[22];
  const float* ln2_s  = (const float*)d_in[23];
  const float* ln2_o  = (const float*)d_in[24];
  const float* out_w  = (const float*)d_in[25];
  const float* out_b  = (const float*)d_in[26];

  float *p_h, *p_qk, *p_v;
  __nv_bfloat16 *p_Ah, *p_Al, *p_Mh, *p_Ml;
  cudaGetSymbolAddress((void**)&p_h,  g_h);
  cudaGetSymbolAddress((void**)&p_qk, g_qk);
  cudaGetSymbolAddress((void**)&p_v,  g_v);
  cudaGetSymbolAddress((void**)&p_Ah, g_Ah);
  cudaGetSymbolAddress((void**)&p_Al, g_Al);
  cudaGetSymbolAddress((void**)&p_Mh, g_Mh);
  cudaGetSymbolAddress((void**)&p_Ml, g_Ml);

  cudaFuncSetAttribute(k_fc_mma, cudaFuncAttributeMaxDynamicSharedMemorySize, FC_SMEM);
  cudaFuncSetAttribute(k_gemm_tc, cudaFuncAttributeMaxDynamicSharedMemorySize, GT_SMEM);

  k_proj<<<ROWS, Ec>>>(x, proj_w, proj_b, ln0_s, ln0_o);
  k_conv<<<dim3(4, Bc), E2c>>>(conv_w);
  k_ln_gelu_conv<<<ROWS, E2c>>>(conv_b, ln1_s, ln1_o);

  for (int l = 0; l < Lc; l++) {
    k_split2<<<(ROWS*E2c)/1024, 256>>>(p_h, p_Ah, p_Al);
    k_gemm_tc<<<dim3(E2c/64, ROWS/128), 256, GT_SMEM>>>(
        p_Ah, p_Al, qk_w + (size_t)l*E2c*E2c, qk_b + l*E2c,
        nullptr, p_qk, nullptr, nullptr, E2c, E2c, 0);
    k_gemm_tc<<<dim3(E2c/64, ROWS/128), 256, GT_SMEM>>>(
        p_Ah, p_Al, v_w + (size_t)l*E2c*E2c, v_b + l*E2c,
        nullptr, p_v, nullptr, nullptr, E2c, E2c, 0);
    k_mass<<<ROWS/32, 256>>>(mass_w + (size_t)l*E2c*Hc, mass_b + l*Hc);
    k_attn<<<Bc*Hc, Sc>>>();
    k_res_ln_gelu<<<ROWS, E2c>>>(norm_s + l*E2c, norm_o + l*E2c);
  }

  // MLP: split h, w1 (gelu -> bf16 pair), w2 (+residual)
  k_split2<<<(ROWS*E2c)/1024, 256>>>(p_h, p_Ah, p_Al);
  k_gemm_tc<<<dim3(MLPH/64, ROWS/128), 256, GT_SMEM>>>(
      p_Ah, p_Al, mlp_w1, mlp_b1, nullptr, nullptr, p_Mh, p_Ml, MLPH, E2c, 1);
  k_gemm_tc<<<dim3(E2c/64, ROWS/128), 256, GT_SMEM>>>(
      p_Mh, p_Ml, mlp_w2, mlp_b2, p_h, p_h, nullptr, nullptr, E2c, MLPH, 2);

  k_split2<<<(ROWS*E2c)/1024, 256>>>(p_h, p_Ah, p_Al);
  k_fc_mma<<<FLATc/FC_BN, 256, FC_SMEM>>>(fc_w, fc_b);
  k_ln_flat<<<Bc, 256>>>(ln2_s, ln2_o);
  k_out<<<dim3(HORc, Bc), 256>>>(out_w, out_b, (float*)d_out);
}

// round 7
// speedup vs baseline: 1.8740x; 1.0984x over previous
#include <cuda_runtime.h>
#include <cuda_bf16.h>
#include <cuda_fp16.h>
#include <math.h>
#include <stdint.h>

#define Bc 128
#define Sc 64
#define FIN 32
#define Ec 96
#define E2c 192
#define Hc 8
#define Dc 24
#define Lc 4
#define HORc 24
#define FLATc (Sc*E2c)          // 12288
#define ROWS (Bc*Sc)            // 8192
#define MLPH (4*Ec)             // 384

// ---------------- scratch (static device globals; no allocation) ----------
__device__ float g_h0[ROWS*Ec];
__device__ float g_conv[ROWS*E2c];
__device__ float g_h[ROWS*E2c];
__device__ float g_qk[ROWS*E2c];
__device__ float g_v[ROWS*E2c];
__device__ float g_mass[Bc*Hc*Sc];
__device__ float g_att[ROWS*E2c];
__device__ float g_f[Bc*FLATc];
__device__ __nv_bfloat16 g_Ah[ROWS*E2c];        // bf16 hi/lo of activations (small GEMMs)
__device__ __nv_bfloat16 g_Al[ROWS*E2c];
__device__ __nv_bfloat16 g_Mh[ROWS*MLPH];       // mlp hidden (bf16 pair)
__device__ __nv_bfloat16 g_Ml[ROWS*MLPH];
__device__ __half g_Fh[ROWS*E2c];               // fp16 hi/lo of final h (fc input)
__device__ __half g_Fl[ROWS*E2c];

// ---------------- helpers ---------------------------------------------------
__device__ __forceinline__ uint32_t smem_u32(const void* p) {
  uint32_t a;
  asm("{ .reg .u64 t; cvta.to.shared.u64 t, %1; cvt.u32.u64 %0, t; }" : "=r"(a) : "l"(p));
  return a;
}
__device__ __forceinline__ float gelu_f(float x) {
  float t = tanhf(0.7978845608028654f * (x + 0.044715f * x * x * x));
  return 0.5f * x * (1.f + t);
}
__device__ __forceinline__ float softplus_f(float x) {
  return fmaxf(x, 0.f) + log1pf(expf(-fabsf(x)));
}
__device__ __forceinline__ void blk_reduce2(float& a, float& b) {
  __shared__ float ra[256], rb[256];
  int t = threadIdx.x, n = blockDim.x;
  ra[t] = a; rb[t] = b;
  __syncthreads();
  #pragma unroll
  for (int s = 128; s > 0; s >>= 1) {
    if (t < s && t + s < n) { ra[t] += ra[t+s]; rb[t] += rb[t+s]; }
    __syncthreads();
  }
  a = ra[0]; b = rb[0];
}
__device__ __forceinline__ void split2(float a, float b, uint32_t& ph, uint32_t& pl) {
  __nv_bfloat16 ha = __float2bfloat16(a), hb = __float2bfloat16(b);
  float ra = a - __bfloat162float(ha), rb = b - __bfloat162float(hb);
  ph = ((uint32_t)__bfloat16_as_ushort(hb) << 16) | __bfloat16_as_ushort(ha);
  pl = ((uint32_t)__bfloat16_as_ushort(__float2bfloat16(rb)) << 16)
       | __bfloat16_as_ushort(__float2bfloat16(ra));
}
__device__ __forceinline__ void split2h(float a, float b, uint32_t& ph, uint32_t& pl) {
  __half ha = __float2half_rn(a), hb = __float2half_rn(b);
  float ra = a - __half2float(ha), rb = b - __half2float(hb);
  ph = ((uint32_t)__half_as_ushort(hb) << 16) | __half_as_ushort(ha);
  pl = ((uint32_t)__half_as_ushort(__float2half_rn(rb)) << 16)
       | __half_as_ushort(__float2half_rn(ra));
}
__device__ __forceinline__ uint32_t pack2h(float a, float b) {
  __half2 h = __floats2half2_rn(a, b);
  return *(uint32_t*)&h;
}
#define MMA16816(d, a, b) \
  asm volatile("mma.sync.aligned.m16n8k16.row.col.f32.bf16.bf16.f32 " \
    "{%0,%1,%2,%3}, {%4,%5,%6,%7}, {%8,%9}, {%0,%1,%2,%3};" \
    : "+f"((d)[0]), "+f"((d)[1]), "+f"((d)[2]), "+f"((d)[3]) \
    : "r"((a).x), "r"((a).y), "r"((a).z), "r"((a).w), "r"((b).x), "r"((b).y))
#define MMAH16816(d, a, b) \
  asm volatile("mma.sync.aligned.m16n8k16.row.col.f32.f16.f16.f32 " \
    "{%0,%1,%2,%3}, {%4,%5,%6,%7}, {%8,%9}, {%0,%1,%2,%3};" \
    : "+f"((d)[0]), "+f"((d)[1]), "+f"((d)[2]), "+f"((d)[3]) \
    : "r"((a).x), "r"((a).y), "r"((a).z), "r"((a).w), "r"((b).x), "r"((b).y))
__device__ __forceinline__ void cp16(uint32_t d, const void* s) {
  asm volatile("cp.async.cg.shared.global [%0], [%1], 16;" :: "r"(d), "l"(s));
}

// ---------------- stage 1: proj -> LN -> gelu -------------------------------
__global__ void k_proj(const float* __restrict__ x, const float* __restrict__ w,
                       const float* __restrict__ bias, const float* __restrict__ ls,
                       const float* __restrict__ lo) {
  int row = blockIdx.x;
  int e = threadIdx.x;
  __shared__ float xs[FIN];
  if (e < FIN) xs[e] = x[row*FIN + e];
  __syncthreads();
  float acc = bias[e];
  #pragma unroll
  for (int k = 0; k < FIN; k++) acc = fmaf(xs[k], w[k*Ec + e], acc);
  float s1 = acc, s2 = acc*acc;
  blk_reduce2(s1, s2);
  float mu = s1 * (1.f/Ec);
  float var = s2 * (1.f/Ec) - mu*mu;
  float y = (acc - mu) * rsqrtf(var + 1e-5f) * ls[e] + lo[e];
  g_h0[row*Ec + e] = gelu_f(y);
}

// ---------------- stage 2: 4x4 SAME conv ------------------------------------
__global__ void k_conv(const float* __restrict__ cw) {
  int i  = blockIdx.y;
  int j0 = blockIdx.x * 16;
  int oc = threadIdx.x;
  __shared__ float sp[4][19*Ec];
  for (int idx = oc; idx < 4*19*Ec; idx += E2c) {
    int di  = idx / (19*Ec);
    int rem = idx - di*19*Ec;
    int col = rem / Ec;
    int c   = rem - col*Ec;
    int gi = i - 1 + di;
    int gj = j0 - 1 + col;
    float v = 0.f;
    if (gi >= 0 && gi < Bc && gj >= 0 && gj < Sc)
      v = g_h0[(gi*Sc + gj)*Ec + c];
    sp[di][col*Ec + c] = v;
  }
  __syncthreads();
  float acc[16];
  #pragma unroll
  for (int j = 0; j < 16; j++) acc[j] = 0.f;
  for (int di = 0; di < 4; di++) {
    for (int c = 0; c < Ec; c++) {
      float pv[19];
      #pragma unroll
      for (int t = 0; t < 19; t++) pv[t] = sp[di][t*Ec + c];
      #pragma unroll
      for (int dj = 0; dj < 4; dj++) {
        float wv = cw[((di*4 + dj)*Ec + c)*E2c + oc];
        #pragma unroll
        for (int j = 0; j < 16; j++) acc[j] = fmaf(pv[j + dj], wv, acc[j]);
      }
    }
  }
  #pragma unroll
  for (int j = 0; j < 16; j++)
    g_conv[(i*Sc + j0 + j)*E2c + oc] = acc[j];
}

// ---------------- stage 3: conv bias -> LN -> gelu (+ bf16 split fused) -----
__global__ void k_ln_gelu_conv(const float* __restrict__ cb,
                               const float* __restrict__ ls, const float* __restrict__ lo) {
  int row = blockIdx.x; int e = threadIdx.x;
  int idx = row*E2c + e;
  float v = g_conv[idx] + cb[e];
  float s1 = v, s2 = v*v;
  blk_reduce2(s1, s2);
  float mu = s1 * (1.f/E2c);
  float var = s2 * (1.f/E2c) - mu*mu;
  float y = gelu_f((v - mu) * rsqrtf(var + 1e-5f) * ls[e] + lo[e]);
  g_h[idx] = y;
  __nv_bfloat16 hi = __float2bfloat16(y);
  g_Ah[idx] = hi;
  g_Al[idx] = __float2bfloat16(y - __bfloat162float(hi));
}

// ---------------- tensor-core small GEMM (bf16 3-product) --------------------
// mode 0: C = acc+bias   mode 1: Oh/Ol = bf16split(gelu(acc+bias))
// mode 2: C = acc+bias+res, plus fp16 split -> Fh/Fl
#define GT_APAD 80
#define GT_OFFAL 10240
#define GT_OFFW 20480
#define GT_STSZ 28672
#define GT_CV 57344
#define GT_CVLO 4608
#define GT_WPAD 144
#define GT_SMEM 66560

__global__ void __launch_bounds__(256) k_gemm_tc(
    const __nv_bfloat16* __restrict__ Ah, const __nv_bfloat16* __restrict__ Al,
    const float* __restrict__ W, const float* __restrict__ bias,
    const float* __restrict__ res, float* __restrict__ C,
    __nv_bfloat16* __restrict__ Oh, __nv_bfloat16* __restrict__ Ol,
    __half* __restrict__ Fh, __half* __restrict__ Fl,
    int N, int K, int mode) {
  extern __shared__ char smc[];
  uint32_t sb = smem_u32(smc);
  int tid = threadIdx.x, lane = tid & 31, wp = tid >> 5;
  int warpM = wp >> 1, warpN = wp & 1;
  int n0 = blockIdx.x * 64, m0 = blockIdx.y * 128;
  int KIT = K >> 5;

  float acc[2][4][4];
  #pragma unroll
  for (int i = 0; i < 2; i++)
    #pragma unroll
    for (int j = 0; j < 4; j++)
      #pragma unroll
      for (int c = 0; c < 4; c++) acc[i][j][c] = 0.f;

  auto load_stage = [&](int slot, int k0) {
    uint32_t st = sb + slot*GT_STSZ;
    #pragma unroll
    for (int t = 0; t < 2; t++) {
      int g = tid*2 + t;
      int m = g >> 2, c = g & 3;
      uint32_t d = st + m*GT_APAD + c*16;
      size_t src = (size_t)(m0 + m)*K + k0 + c*8;
      cp16(d, Ah + src);
      cp16(d + GT_OFFAL, Al + src);
    }
    #pragma unroll
    for (int t = 0; t < 2; t++) {
      int g = tid*2 + t;
      int k = g >> 4, c = g & 15;
      cp16(st + GT_OFFW + k*256 + c*16, W + (size_t)(k0 + k)*N + n0 + c*4);
    }
  };

  load_stage(0, 0);
  asm volatile("cp.async.commit_group;" ::: "memory");

  int arow = warpM*32 + (lane & 15);
  int ckrow = tid >> 3, cseg = tid & 7;

  for (int it = 0; it < KIT; it++) {
    asm volatile("cp.async.wait_group 0;" ::: "memory");
    __syncthreads();
    if (it + 1 < KIT) load_stage((it + 1) & 1, (it + 1)*32);
    asm volatile("cp.async.commit_group;" ::: "memory");
    {
      uint32_t src = sb + (it & 1)*GT_STSZ + GT_OFFW + (uint32_t)ckrow*256 + cseg*32;
      uint32_t dh  = sb + GT_CV + (uint32_t)ckrow*GT_WPAD + cseg*16;
      float4 f0, f1;
      asm volatile("ld.shared.v4.f32 {%0,%1,%2,%3}, [%4];"
        : "=f"(f0.x), "=f"(f0.y), "=f"(f0.z), "=f"(f0.w) : "r"(src));
      asm volatile("ld.shared.v4.f32 {%0,%1,%2,%3}, [%4];"
        : "=f"(f1.x), "=f"(f1.y), "=f"(f1.z), "=f"(f1.w) : "r"(src + 16));
      uint32_t h[4], l[4];
      split2(f0.x, f0.y, h[0], l[0]);
      split2(f0.z, f0.w, h[1], l[1]);
      split2(f1.x, f1.y, h[2], l[2]);
      split2(f1.z, f1.w, h[3], l[3]);
      asm volatile("st.shared.v4.b32 [%0], {%1,%2,%3,%4};"
        :: "r"(dh), "r"(h[0]), "r"(h[1]), "r"(h[2]), "r"(h[3]));
      asm volatile("st.shared.v4.b32 [%0], {%1,%2,%3,%4};"
        :: "r"(dh + GT_CVLO), "r"(l[0]), "r"(l[1]), "r"(l[2]), "r"(l[3]));
    }
    __syncthreads();
    uint32_t st = sb + (it & 1)*GT_STSZ;
    uint32_t cv = sb + GT_CV;
    #pragma unroll
    for (int ks = 0; ks < 2; ks++) {
      uint4 fah[2], fal[2];
      int c = ks*2 + (lane >> 4);
      #pragma unroll
      for (int i = 0; i < 2; i++) {
        uint32_t ad = st + (uint32_t)(arow + i*16)*GT_APAD + c*16;
        asm volatile("ldmatrix.sync.aligned.m8n8.x4.shared.b16 {%0,%1,%2,%3}, [%4];"
          : "=r"(fah[i].x), "=r"(fah[i].y), "=r"(fah[i].z), "=r"(fah[i].w) : "r"(ad));
        asm volatile("ldmatrix.sync.aligned.m8n8.x4.shared.b16 {%0,%1,%2,%3}, [%4];"
          : "=r"(fal[i].x), "=r"(fal[i].y), "=r"(fal[i].z), "=r"(fal[i].w) : "r"(ad + GT_OFFAL));
      }
      uint2 fwh[4], fwl[4];
      int kl = ks*16 + (lane & 15);
      #pragma unroll
      for (int j = 0; j < 4; j++) {
        uint32_t wd = cv + (uint32_t)kl*GT_WPAD + (uint32_t)(warpN*32 + j*8)*2;
        asm volatile("ldmatrix.sync.aligned.m8n8.x2.trans.shared.b16 {%0,%1}, [%2];"
          : "=r"(fwh[j].x), "=r"(fwh[j].y) : "r"(wd));
        asm volatile("ldmatrix.sync.aligned.m8n8.x2.trans.shared.b16 {%0,%1}, [%2];"
          : "=r"(fwl[j].x), "=r"(fwl[j].y) : "r"(wd + GT_CVLO));
      }
      #pragma unroll
      for (int i = 0; i < 2; i++)
        #pragma unroll
        for (int j = 0; j < 4; j++) MMA16816(acc[i][j], fah[i], fwh[j]);
      #pragma unroll
      for (int i = 0; i < 2; i++)
        #pragma unroll
        for (int j = 0; j < 4; j++) MMA16816(acc[i][j], fal[i], fwh[j]);
      #pragma unroll
      for (int i = 0; i < 2; i++)
        #pragma unroll
        for (int j = 0; j < 4; j++) MMA16816(acc[i][j], fah[i], fwl[j]);
    }
  }

  int g = lane >> 2, q = lane & 3;
  #pragma unroll
  for (int i = 0; i < 2; i++) {
    int m = m0 + warpM*32 + i*16 + g;
    #pragma unroll
    for (int j = 0; j < 4; j++) {
      int n = n0 + warpN*32 + j*8 + q*2;
      float b0 = bias[n], b1 = bias[n+1];
      float v00 = acc[i][j][0] + b0, v01 = acc[i][j][1] + b1;
      float v10 = acc[i][j][2] + b0, v11 = acc[i][j][3] + b1;
      if (mode == 1) {
        uint32_t ph0, pl0, ph1, pl1;
        split2(gelu_f(v00), gelu_f(v01), ph0, pl0);
        split2(gelu_f(v10), gelu_f(v11), ph1, pl1);
        *(uint32_t*)(Oh + (size_t)m*N + n)     = ph0;
        *(uint32_t*)(Ol + (size_t)m*N + n)     = pl0;
        *(uint32_t*)(Oh + (size_t)(m+8)*N + n) = ph1;
        *(uint32_t*)(Ol + (size_t)(m+8)*N + n) = pl1;
      } else {
        if (mode == 2) {
          float2 r0 = *(const float2*)(res + (size_t)m*N + n);
          float2 r1 = *(const float2*)(res + (size_t)(m+8)*N + n);
          v00 += r0.x; v01 += r0.y; v10 += r1.x; v11 += r1.y;
          uint32_t ph0, pl0, ph1, pl1;
          split2h(v00, v01, ph0, pl0);
          split2h(v10, v11, ph1, pl1);
          *(uint32_t*)(Fh + (size_t)m*N + n)     = ph0;
          *(uint32_t*)(Fl + (size_t)m*N + n)     = pl0;
          *(uint32_t*)(Fh + (size_t)(m+8)*N + n) = ph1;
          *(uint32_t*)(Fl + (size_t)(m+8)*N + n) = pl1;
        }
        *(float2*)(C + (size_t)m*N + n)     = make_float2(v00, v01);
        *(float2*)(C + (size_t)(m+8)*N + n) = make_float2(v10, v11);
      }
    }
  }
}

// ---------------- mass head --------------------------------------------------
__global__ void k_mass(const float* __restrict__ mw, const float* __restrict__ mb) {
  __shared__ float hs[32][E2c+1];
  __shared__ float ws[E2c*Hc];
  int r0 = blockIdx.x * 32;
  int tid = threadIdx.x;
  for (int idx = tid; idx < 32*E2c; idx += 256) {
    int r = idx / E2c, k = idx - (idx / E2c)*E2c;
    hs[r][k] = g_h[(r0 + r)*E2c + k];
  }
  for (int idx = tid; idx < E2c*Hc; idx += 256) ws[idx] = mw[idx];
  __syncthreads();
  int r = tid >> 3, hh = tid & 7;
  float acc = mb[hh];
  #pragma unroll 4
  for (int k = 0; k < E2c; k++) acc = fmaf(hs[r][k], ws[k*Hc + hh], acc);
  int row = r0 + r; int b = row >> 6, s = row & 63;
  g_mass[(b*Hc + hh)*Sc + s] = softplus_f(acc);
}

// ---------------- gravity attention core -------------------------------------
__global__ void k_attn() {
  int bh = blockIdx.x; int b = bh >> 3, hh = bh & 7;
  int i = threadIdx.x;
  __shared__ float qs[Sc][Dc+1];
  __shared__ float vs[Sc][Dc+1];
  __shared__ float ms[Sc];
  __shared__ float sq[Sc];
  const float* qbase = g_qk + (size_t)(b*Sc)*E2c + hh*Dc;
  const float* vbase = g_v  + (size_t)(b*Sc)*E2c + hh*Dc;
  float qi[Dc];
  float ssq = 0.f;
  #pragma unroll
  for (int d = 0; d < Dc; d++) {
    float q = qbase[i*E2c + d];
    qs[i][d] = q; qi[d] = q; ssq = fmaf(q, q, ssq);
    vs[i][d] = vbase[i*E2c + d];
  }
  sq[i] = ssq;
  ms[i] = g_mass[(b*Hc + hh)*Sc + i];
  __syncthreads();
  float mi = ms[i];
  float mmax = -INFINITY, l = 0.f;
  float acc[Dc];
  #pragma unroll
  for (int d = 0; d < Dc; d++) acc[d] = 0.f;
  for (int j = 0; j < Sc; j++) {
    float dot = 0.f;
    #pragma unroll
    for (int d = 0; d < Dc; d++) dot = fmaf(qi[d], qs[j][d], dot);
    float d2 = fmaxf(ssq + sq[j] - 2.f*dot, 0.f) + 1e-6f;
    float sc = mi * ms[j] / d2;
    float mn = fmaxf(mmax, sc);
    float scale = __expf(mmax - mn);
    float p = __expf(sc - mn);
    l = l*scale + p;
    #pragma unroll
    for (int d = 0; d < Dc; d++) acc[d] = fmaf(p, vs[j][d], acc[d]*scale);
    mmax = mn;
  }
  float inv = 1.f / l;
  float* obase = g_att + (size_t)(b*Sc + i)*E2c + hh*Dc;
  #pragma unroll
  for (int d = 0; d < Dc; d++) obase[d] = acc[d] * inv;
}

// ---------------- residual + LN + gelu (+ bf16 split fused) ------------------
__global__ void k_res_ln_gelu(const float* __restrict__ ls, const float* __restrict__ lo) {
  int row = blockIdx.x; int e = threadIdx.x;
  int idx = row*E2c + e;
  float v = g_h[idx] + g_att[idx];
  float s1 = v, s2 = v*v;
  blk_reduce2(s1, s2);
  float mu = s1 * (1.f/E2c);
  float var = s2 * (1.f/E2c) - mu*mu;
  float y = gelu_f((v - mu) * rsqrtf(var + 1e-5f) * ls[e] + lo[e]);
  g_h[idx] = y;
  __nv_bfloat16 hi = __float2bfloat16(y);
  g_Ah[idx] = hi;
  g_Al[idx] = __float2bfloat16(y - __bfloat162float(hi));
}

// ---------------- fc GEMM: fp16 2-product, cp.async 4-stage ------------------
// D[128, 96-slab] = (Ah+Al fp16) @ fp16(W); error ~W-rounding (2^-11/sqrt3).
#define FC_BN 96
#define FC_BK 32
#define FC_IT (FLATc/FC_BK)     // 384
#define FC_ST 4
#define A_PAD 80
#define W_PAD 208
#define OFF_AL 10240
#define OFF_W32 20480
#define ST_SZ  32768
#define CV_OFF (FC_ST*ST_SZ)    // 131072
#define CV_BUF 6656             // Wh only: 32 rows x 208
#define FC_SMEM (CV_OFF + 2*CV_BUF)   // 144384

__device__ __forceinline__ void fc_stage_load(uint32_t sb, int slot, int k0, int n0,
                                              const float* __restrict__ W, int tid) {
  uint32_t st = sb + slot*ST_SZ;
  {
    int g0 = tid * 2;
    #pragma unroll
    for (int t = 0; t < 2; t++) {
      int g = g0 + t;
      int m = g >> 2, c = g & 3;
      uint32_t d = st + m*A_PAD + c*16;
      size_t src = (size_t)m*FLATc + k0 + c*8;
      cp16(d, g_Fh + src);
      cp16(d + OFF_AL, g_Fl + src);
    }
  }
  #pragma unroll
  for (int t = 0; t < 3; t++) {
    int g = tid + t*256;
    int k = g / 24, c = g - k*24;
    uint32_t d = st + OFF_W32 + k*384 + c*16;
    cp16(d, W + (size_t)(k0 + k)*FLATc + n0 + c*4);
  }
}

__global__ void __launch_bounds__(256, 1) k_fc_mma(const float* __restrict__ W,
                                                   const float* __restrict__ bias) {
  extern __shared__ char smc[];
  uint32_t sb = smem_u32(smc);
  int tid = threadIdx.x, lane = tid & 31, wp = tid >> 5;
  int warpM = wp >> 1, warpN = wp & 1;
  int n0 = blockIdx.x * FC_BN;

  float acc[2][6][4];
  #pragma unroll
  for (int i = 0; i < 2; i++)
    #pragma unroll
    for (int j = 0; j < 6; j++)
      #pragma unroll
      for (int c = 0; c < 4; c++) acc[i][j][c] = 0.f;

  #pragma unroll
  for (int s = 0; s < FC_ST - 1; s++) {
    fc_stage_load(sb, s, s*FC_BK, n0, W, tid);
    asm volatile("cp.async.commit_group;" ::: "memory");
  }

  int arow = warpM*32 + (lane & 15);
  int ckrow = tid >> 3, cseg = tid & 7;

  for (int it = 0; it < FC_IT; it++) {
    asm volatile("cp.async.wait_group 2;" ::: "memory");
    __syncthreads();

    if (it + FC_ST - 1 < FC_IT) {
      fc_stage_load(sb, (it + FC_ST - 1) & 3, (it + FC_ST - 1)*FC_BK, n0, W, tid);
    }
    asm volatile("cp.async.commit_group;" ::: "memory");

    // convert fp32 W tile (stage it) -> fp16 Wh buffer (it&1)
    {
      uint32_t src = sb + (it & 3)*ST_SZ + OFF_W32 + (uint32_t)ckrow*384 + cseg*48;
      uint32_t dh  = sb + CV_OFF + (it & 1)*CV_BUF + (uint32_t)ckrow*W_PAD + cseg*24;
      float4 f0, f1, f2;
      asm volatile("ld.shared.v4.f32 {%0,%1,%2,%3}, [%4];"
        : "=f"(f0.x), "=f"(f0.y), "=f"(f0.z), "=f"(f0.w) : "r"(src));
      asm volatile("ld.shared.v4.f32 {%0,%1,%2,%3}, [%4];"
        : "=f"(f1.x), "=f"(f1.y), "=f"(f1.z), "=f"(f1.w) : "r"(src + 16));
      asm volatile("ld.shared.v4.f32 {%0,%1,%2,%3}, [%4];"
        : "=f"(f2.x), "=f"(f2.y), "=f"(f2.z), "=f"(f2.w) : "r"(src + 32));
      uint32_t h0 = pack2h(f0.x, f0.y), h1 = pack2h(f0.z, f0.w);
      uint32_t h2 = pack2h(f1.x, f1.y), h3 = pack2h(f1.z, f1.w);
      uint32_t h4 = pack2h(f2.x, f2.y), h5 = pack2h(f2.z, f2.w);
      asm volatile("st.shared.v2.b32 [%0], {%1,%2};" :: "r"(dh),      "r"(h0), "r"(h1));
      asm volatile("st.shared.v2.b32 [%0], {%1,%2};" :: "r"(dh + 8),  "r"(h2), "r"(h3));
      asm volatile("st.shared.v2.b32 [%0], {%1,%2};" :: "r"(dh + 16), "r"(h4), "r"(h5));
    }
    __syncthreads();

    uint32_t st = sb + (it & 3)*ST_SZ;
    uint32_t cv = sb + CV_OFF + (it & 1)*CV_BUF;
    #pragma unroll
    for (int ks = 0; ks < 2; ks++) {
      uint4 fah[2], fal[2];
      int c = ks*2 + (lane >> 4);
      #pragma unroll
      for (int i = 0; i < 2; i++) {
        uint32_t ad = st + (uint32_t)(arow + i*16)*A_PAD + c*16;
        asm volatile("ldmatrix.sync.aligned.m8n8.x4.shared.b16 {%0,%1,%2,%3}, [%4];"
          : "=r"(fah[i].x), "=r"(fah[i].y), "=r"(fah[i].z), "=r"(fah[i].w) : "r"(ad));
        asm volatile("ldmatrix.sync.aligned.m8n8.x4.shared.b16 {%0,%1,%2,%3}, [%4];"
          : "=r"(fal[i].x), "=r"(fal[i].y), "=r"(fal[i].z), "=r"(fal[i].w) : "r"(ad + OFF_AL));
      }
      uint2 fwh[6];
      int kl = ks*16 + (lane & 15);
      #pragma unroll
      for (int j = 0; j < 6; j++) {
        uint32_t wd = cv + (uint32_t)kl*W_PAD + (uint32_t)(warpN*48 + j*8)*2;
        asm volatile("ldmatrix.sync.aligned.m8n8.x2.trans.shared.b16 {%0,%1}, [%2];"
          : "=r"(fwh[j].x), "=r"(fwh[j].y) : "r"(wd));
      }
      #pragma unroll
      for (int i = 0; i < 2; i++)
        #pragma unroll
        for (int j = 0; j < 6; j++) MMAH16816(acc[i][j], fah[i], fwh[j]);
      #pragma unroll
      for (int i = 0; i < 2; i++)
        #pragma unroll
        for (int j = 0; j < 6; j++) MMAH16816(acc[i][j], fal[i], fwh[j]);
    }
  }

  // epilogue: bias + gelu -> g_f
  int g = lane >> 2, q = lane & 3;
  #pragma unroll
  for (int i = 0; i < 2; i++) {
    int m = warpM*32 + i*16 + g;
    #pragma unroll
    for (int j = 0; j < 6; j++) {
      int n = n0 + warpN*48 + j*8 + q*2;
      float b0 = bias[n], b1 = bias[n+1];
      float2 r0, r1;
      r0.x = gelu_f(acc[i][j][0] + b0);
      r0.y = gelu_f(acc[i][j][1] + b1);
      r1.x = gelu_f(acc[i][j][2] + b0);
      r1.y = gelu_f(acc[i][j][3] + b1);
      *(float2*)(g_f + (size_t)m*FLATc + n)       = r0;
      *(float2*)(g_f + (size_t)(m + 8)*FLATc + n) = r1;
    }
  }
}

// ---------------- LN over FLAT -----------------------------------------------
__global__ void k_ln_flat(const float* __restrict__ ls, const float* __restrict__ lo) {
  int b = blockIdx.x; int t = threadIdx.x;
  float* frow = g_f + (size_t)b*FLATc;
  float s1 = 0.f, s2 = 0.f;
  for (int k = t; k < FLATc; k += 256) { float v = frow[k]; s1 += v; s2 += v*v; }
  blk_reduce2(s1, s2);
  float mu = s1 * (1.f/FLATc);
  float var = s2 * (1.f/FLATc) - mu*mu;
  float rs = rsqrtf(var + 1e-5f);
  for (int k = t; k < FLATc; k += 256) {
    float v = frow[k];
    frow[k] = (v - mu) * rs * ls[k] + lo[k];
  }
}

// ---------------- final out GEMM ---------------------------------------------
__global__ void k_out(const float* __restrict__ ow, const float* __restrict__ ob,
                      float* __restrict__ out) {
  int o = blockIdx.x, b = blockIdx.y;
  int t = threadIdx.x;
  const float* frow = g_f + (size_t)b*FLATc;
  float s1 = 0.f, s2 = 0.f;
  for (int k = t; k < FLATc; k += 256) s1 = fmaf(frow[k], ow[(size_t)k*HORc + o], s1);
  blk_reduce2(s1, s2);
  if (t == 0) out[b*HORc + o] = s1 + ob[o];
}

// ---------------- launch ------------------------------------------------------
extern "C" void kernel_launch(void* const* d_in, const int* in_sizes, int n_in,
                              void* d_out, int out_size) {
  const float* x      = (const float*)d_in[0];
  const float* proj_w = (const float*)d_in[1];
  const float* proj_b = (const float*)d_in[2];
  const float* ln0_s  = (const float*)d_in[3];
  const float* ln0_o  = (const float*)d_in[4];
  const float* conv_w = (const float*)d_in[5];
  const float* conv_b = (const float*)d_in[6];
  const float* ln1_s  = (const float*)d_in[7];
  const float* ln1_o  = (const float*)d_in[8];
  const float* qk_w   = (const float*)d_in[9];
  const float* qk_b   = (const float*)d_in[10];
  const float* mass_w = (const float*)d_in[11];
  const float* mass_b = (const float*)d_in[12];
  const float* v_w    = (const float*)d_in[13];
  const float* v_b    = (const float*)d_in[14];
  const float* norm_s = (const float*)d_in[15];
  const float* norm_o = (const float*)d_in[16];
  const float* mlp_w1 = (const float*)d_in[17];
  const float* mlp_b1 = (const float*)d_in[18];
  const float* mlp_w2 = (const float*)d_in[19];
  const float* mlp_b2 = (const float*)d_in[20];
  const float* fc_w   = (const float*)d_in[21];
  const float* fc_b   = (const float*)d_in[22];
  const float* ln2_s  = (const float*)d_in[23];
  const float* ln2_o  = (const float*)d_in[24];
  const float* out_w  = (const float*)d_in[25];
  const float* out_b  = (const float*)d_in[26];

  float *p_h, *p_qk, *p_v;
  __nv_bfloat16 *p_Ah, *p_Al, *p_Mh, *p_Ml;
  __half *p_Fh, *p_Fl;
  cudaGetSymbolAddress((void**)&p_h,  g_h);
  cudaGetSymbolAddress((void**)&p_qk, g_qk);
  cudaGetSymbolAddress((void**)&p_v,  g_v);
  cudaGetSymbolAddress((void**)&p_Ah, g_Ah);
  cudaGetSymbolAddress((void**)&p_Al, g_Al);
  cudaGetSymbolAddress((void**)&p_Mh, g_Mh);
  cudaGetSymbolAddress((void**)&p_Ml, g_Ml);
  cudaGetSymbolAddress((void**)&p_Fh, g_Fh);
  cudaGetSymbolAddress((void**)&p_Fl, g_Fl);

  cudaFuncSetAttribute(k_fc_mma, cudaFuncAttributeMaxDynamicSharedMemorySize, FC_SMEM);
  cudaFuncSetAttribute(k_gemm_tc, cudaFuncAttributeMaxDynamicSharedMemorySize, GT_SMEM);

  k_proj<<<ROWS, Ec>>>(x, proj_w, proj_b, ln0_s, ln0_o);
  k_conv<<<dim3(4, Bc), E2c>>>(conv_w);
  k_ln_gelu_conv<<<ROWS, E2c>>>(conv_b, ln1_s, ln1_o);

  for (int l = 0; l < Lc; l++) {
    k_gemm_tc<<<dim3(E2c/64, ROWS/128), 256, GT_SMEM>>>(
        p_Ah, p_Al, qk_w + (size_t)l*E2c*E2c, qk_b + l*E2c,
        nullptr, p_qk, nullptr, nullptr, nullptr, nullptr, E2c, E2c, 0);
    k_gemm_tc<<<dim3(E2c/64, ROWS/128), 256, GT_SMEM>>>(
        p_Ah, p_Al, v_w + (size_t)l*E2c*E2c, v_b + l*E2c,
        nullptr, p_v, nullptr, nullptr, nullptr, nullptr, E2c, E2c, 0);
    k_mass<<<ROWS/32, 256>>>(mass_w + (size_t)l*E2c*Hc, mass_b + l*Hc);
    k_attn<<<Bc*Hc, Sc>>>();
    k_res_ln_gelu<<<ROWS, E2c>>>(norm_s + l*E2c, norm_o + l*E2c);
  }

  // MLP: w1 (gelu -> bf16 pair), w2 (+residual, + fp16 split for fc)
  k_gemm_tc<<<dim3(MLPH/64, ROWS/128), 256, GT_SMEM>>>(
      p_Ah, p_Al, mlp_w1, mlp_b1, nullptr, nullptr, p_Mh, p_Ml,
      nullptr, nullptr, MLPH, E2c, 1);
  k_gemm_tc<<<dim3(E2c/64, ROWS/128), 256, GT_SMEM>>>(
      p_Mh, p_Ml, mlp_w2, mlp_b2, p_h, p_h, nullptr, nullptr,
      p_Fh, p_Fl, E2c, MLPH, 2);

  k_fc_mma<<<FLATc/FC_BN, 256, FC_SMEM>>>(fc_w, fc_b);
  k_ln_flat<<<Bc, 256>>>(ln2_s, ln2_o);
  k_out<<<dim3(HORc, Bc), 256>>>(out_w, out_b, (float*)d_out);
}

// round 8
// speedup vs baseline: 2.0728x; 1.1061x over previous
#include <cuda_runtime.h>
#include <cuda_bf16.h>
#include <cuda_fp16.h>
#include <math.h>
#include <stdint.h>

#define Bc 128
#define Sc 64
#define FIN 32
#define Ec 96
#define E2c 192
#define Hc 8
#define Dc 24
#define Lc 4
#define HORc 24
#define FLATc (Sc*E2c)          // 12288
#define ROWS (Bc*Sc)            // 8192
#define MLPH (4*Ec)             // 384

// ---------------- scratch (static device globals; no allocation) ----------
__device__ float g_h0[ROWS*Ec];
__device__ float g_conv[ROWS*E2c];
__device__ float g_h[ROWS*E2c];
__device__ float g_qk[ROWS*E2c];
__device__ float g_v[ROWS*E2c];
__device__ float g_mass[Bc*Hc*Sc];
__device__ float g_att[ROWS*E2c];
__device__ float g_f[Bc*FLATc];
__device__ __nv_bfloat16 g_Ah[ROWS*E2c];        // bf16 hi/lo of activations (small GEMMs)
__device__ __nv_bfloat16 g_Al[ROWS*E2c];
__device__ __nv_bfloat16 g_Mh[ROWS*MLPH];       // mlp hidden (bf16 pair)
__device__ __nv_bfloat16 g_Ml[ROWS*MLPH];
__device__ __half g_Fh[ROWS*E2c];               // fp16 of final h (fc input)

// ---------------- helpers ---------------------------------------------------
__device__ __forceinline__ uint32_t smem_u32(const void* p) {
  uint32_t a;
  asm("{ .reg .u64 t; cvta.to.shared.u64 t, %1; cvt.u32.u64 %0, t; }" : "=r"(a) : "l"(p));
  return a;
}
__device__ __forceinline__ float gelu_f(float x) {
  float t = tanhf(0.7978845608028654f * (x + 0.044715f * x * x * x));
  return 0.5f * x * (1.f + t);
}
__device__ __forceinline__ float softplus_f(float x) {
  return fmaxf(x, 0.f) + log1pf(expf(-fabsf(x)));
}
__device__ __forceinline__ void blk_reduce2(float& a, float& b) {
  __shared__ float ra[256], rb[256];
  int t = threadIdx.x, n = blockDim.x;
  ra[t] = a; rb[t] = b;
  __syncthreads();
  #pragma unroll
  for (int s = 128; s > 0; s >>= 1) {
    if (t < s && t + s < n) { ra[t] += ra[t+s]; rb[t] += rb[t+s]; }
    __syncthreads();
  }
  a = ra[0]; b = rb[0];
}
__device__ __forceinline__ void split2(float a, float b, uint32_t& ph, uint32_t& pl) {
  __nv_bfloat16 ha = __float2bfloat16(a), hb = __float2bfloat16(b);
  float ra = a - __bfloat162float(ha), rb = b - __bfloat162float(hb);
  ph = ((uint32_t)__bfloat16_as_ushort(hb) << 16) | __bfloat16_as_ushort(ha);
  pl = ((uint32_t)__bfloat16_as_ushort(__float2bfloat16(rb)) << 16)
       | __bfloat16_as_ushort(__float2bfloat16(ra));
}
__device__ __forceinline__ uint32_t pack2h(float a, float b) {
  __half2 h = __floats2half2_rn(a, b);
  return *(uint32_t*)&h;
}
#define MMA16816(d, a, b) \
  asm volatile("mma.sync.aligned.m16n8k16.row.col.f32.bf16.bf16.f32 " \
    "{%0,%1,%2,%3}, {%4,%5,%6,%7}, {%8,%9}, {%0,%1,%2,%3};" \
    : "+f"((d)[0]), "+f"((d)[1]), "+f"((d)[2]), "+f"((d)[3]) \
    : "r"((a).x), "r"((a).y), "r"((a).z), "r"((a).w), "r"((b).x), "r"((b).y))
#define MMAH16816(d, a, b) \
  asm volatile("mma.sync.aligned.m16n8k16.row.col.f32.f16.f16.f32 " \
    "{%0,%1,%2,%3}, {%4,%5,%6,%7}, {%8,%9}, {%0,%1,%2,%3};" \
    : "+f"((d)[0]), "+f"((d)[1]), "+f"((d)[2]), "+f"((d)[3]) \
    : "r"((a).x), "r"((a).y), "r"((a).z), "r"((a).w), "r"((b).x), "r"((b).y))
__device__ __forceinline__ void cp16(uint32_t d, const void* s) {
  asm volatile("cp.async.cg.shared.global [%0], [%1], 16;" :: "r"(d), "l"(s));
}

// ---------------- stage 1: proj -> LN -> gelu -------------------------------
__global__ void k_proj(const float* __restrict__ x, const float* __restrict__ w,
                       const float* __restrict__ bias, const float* __restrict__ ls,
                       const float* __restrict__ lo) {
  int row = blockIdx.x;
  int e = threadIdx.x;
  __shared__ float xs[FIN];
  if (e < FIN) xs[e] = x[row*FIN + e];
  __syncthreads();
  float acc = bias[e];
  #pragma unroll
  for (int k = 0; k < FIN; k++) acc = fmaf(xs[k], w[k*Ec + e], acc);
  float s1 = acc, s2 = acc*acc;
  blk_reduce2(s1, s2);
  float mu = s1 * (1.f/Ec);
  float var = s2 * (1.f/Ec) - mu*mu;
  float y = (acc - mu) * rsqrtf(var + 1e-5f) * ls[e] + lo[e];
  g_h0[row*Ec + e] = gelu_f(y);
}

// ---------------- stage 2: 4x4 SAME conv ------------------------------------
__global__ void k_conv(const float* __restrict__ cw) {
  int i  = blockIdx.y;
  int j0 = blockIdx.x * 16;
  int oc = threadIdx.x;
  __shared__ float sp[4][19*Ec];
  for (int idx = oc; idx < 4*19*Ec; idx += E2c) {
    int di  = idx / (19*Ec);
    int rem = idx - di*19*Ec;
    int col = rem / Ec;
    int c   = rem - col*Ec;
    int gi = i - 1 + di;
    int gj = j0 - 1 + col;
    float v = 0.f;
    if (gi >= 0 && gi < Bc && gj >= 0 && gj < Sc)
      v = g_h0[(gi*Sc + gj)*Ec + c];
    sp[di][col*Ec + c] = v;
  }
  __syncthreads();
  float acc[16];
  #pragma unroll
  for (int j = 0; j < 16; j++) acc[j] = 0.f;
  for (int di = 0; di < 4; di++) {
    for (int c = 0; c < Ec; c++) {
      float pv[19];
      #pragma unroll
      for (int t = 0; t < 19; t++) pv[t] = sp[di][t*Ec + c];
      #pragma unroll
      for (int dj = 0; dj < 4; dj++) {
        float wv = cw[((di*4 + dj)*Ec + c)*E2c + oc];
        #pragma unroll
        for (int j = 0; j < 16; j++) acc[j] = fmaf(pv[j + dj], wv, acc[j]);
      }
    }
  }
  #pragma unroll
  for (int j = 0; j < 16; j++)
    g_conv[(i*Sc + j0 + j)*E2c + oc] = acc[j];
}

// ---------------- stage 3: conv bias -> LN -> gelu (+ bf16 split fused) -----
__global__ void k_ln_gelu_conv(const float* __restrict__ cb,
                               const float* __restrict__ ls, const float* __restrict__ lo) {
  int row = blockIdx.x; int e = threadIdx.x;
  int idx = row*E2c + e;
  float v = g_conv[idx] + cb[e];
  float s1 = v, s2 = v*v;
  blk_reduce2(s1, s2);
  float mu = s1 * (1.f/E2c);
  float var = s2 * (1.f/E2c) - mu*mu;
  float y = gelu_f((v - mu) * rsqrtf(var + 1e-5f) * ls[e] + lo[e]);
  g_h[idx] = y;
  __nv_bfloat16 hi = __float2bfloat16(y);
  g_Ah[idx] = hi;
  g_Al[idx] = __float2bfloat16(y - __bfloat162float(hi));
}

// ---------------- tensor-core small GEMM (bf16 3-product) --------------------
// mode 0: C = acc+bias   mode 1: Oh/Ol = bf16split(gelu(acc+bias))
// mode 2: C = acc+bias+res, plus fp16 -> Fh
#define GT_APAD 80
#define GT_OFFAL 10240
#define GT_OFFW 20480
#define GT_STSZ 28672
#define GT_CV 57344
#define GT_CVLO 4608
#define GT_WPAD 144
#define GT_SMEM 66560

__global__ void __launch_bounds__(256) k_gemm_tc(
    const __nv_bfloat16* __restrict__ Ah, const __nv_bfloat16* __restrict__ Al,
    const float* __restrict__ W, const float* __restrict__ bias,
    const float* __restrict__ res, float* __restrict__ C,
    __nv_bfloat16* __restrict__ Oh, __nv_bfloat16* __restrict__ Ol,
    __half* __restrict__ Fh,
    int N, int K, int mode) {
  extern __shared__ char smc[];
  uint32_t sb = smem_u32(smc);
  int tid = threadIdx.x, lane = tid & 31, wp = tid >> 5;
  int warpM = wp >> 1, warpN = wp & 1;
  int n0 = blockIdx.x * 64, m0 = blockIdx.y * 128;
  int KIT = K >> 5;

  float acc[2][4][4];
  #pragma unroll
  for (int i = 0; i < 2; i++)
    #pragma unroll
    for (int j = 0; j < 4; j++)
      #pragma unroll
      for (int c = 0; c < 4; c++) acc[i][j][c] = 0.f;

  auto load_stage = [&](int slot, int k0) {
    uint32_t st = sb + slot*GT_STSZ;
    #pragma unroll
    for (int t = 0; t < 2; t++) {
      int g = tid*2 + t;
      int m = g >> 2, c = g & 3;
      uint32_t d = st + m*GT_APAD + c*16;
      size_t src = (size_t)(m0 + m)*K + k0 + c*8;
      cp16(d, Ah + src);
      cp16(d + GT_OFFAL, Al + src);
    }
    #pragma unroll
    for (int t = 0; t < 2; t++) {
      int g = tid*2 + t;
      int k = g >> 4, c = g & 15;
      cp16(st + GT_OFFW + k*256 + c*16, W + (size_t)(k0 + k)*N + n0 + c*4);
    }
  };

  load_stage(0, 0);
  asm volatile("cp.async.commit_group;" ::: "memory");

  int arow = warpM*32 + (lane & 15);
  int ckrow = tid >> 3, cseg = tid & 7;

  for (int it = 0; it < KIT; it++) {
    asm volatile("cp.async.wait_group 0;" ::: "memory");
    __syncthreads();
    if (it + 1 < KIT) load_stage((it + 1) & 1, (it + 1)*32);
    asm volatile("cp.async.commit_group;" ::: "memory");
    {
      uint32_t src = sb + (it & 1)*GT_STSZ + GT_OFFW + (uint32_t)ckrow*256 + cseg*32;
      uint32_t dh  = sb + GT_CV + (uint32_t)ckrow*GT_WPAD + cseg*16;
      float4 f0, f1;
      asm volatile("ld.shared.v4.f32 {%0,%1,%2,%3}, [%4];"
        : "=f"(f0.x), "=f"(f0.y), "=f"(f0.z), "=f"(f0.w) : "r"(src));
      asm volatile("ld.shared.v4.f32 {%0,%1,%2,%3}, [%4];"
        : "=f"(f1.x), "=f"(f1.y), "=f"(f1.z), "=f"(f1.w) : "r"(src + 16));
      uint32_t h[4], l[4];
      split2(f0.x, f0.y, h[0], l[0]);
      split2(f0.z, f0.w, h[1], l[1]);
      split2(f1.x, f1.y, h[2], l[2]);
      split2(f1.z, f1.w, h[3], l[3]);
      asm volatile("st.shared.v4.b32 [%0], {%1,%2,%3,%4};"
        :: "r"(dh), "r"(h[0]), "r"(h[1]), "r"(h[2]), "r"(h[3]));
      asm volatile("st.shared.v4.b32 [%0], {%1,%2,%3,%4};"
        :: "r"(dh + GT_CVLO), "r"(l[0]), "r"(l[1]), "r"(l[2]), "r"(l[3]));
    }
    __syncthreads();
    uint32_t st = sb + (it & 1)*GT_STSZ;
    uint32_t cv = sb + GT_CV;
    #pragma unroll
    for (int ks = 0; ks < 2; ks++) {
      uint4 fah[2], fal[2];
      int c = ks*2 + (lane >> 4);
      #pragma unroll
      for (int i = 0; i < 2; i++) {
        uint32_t ad = st + (uint32_t)(arow + i*16)*GT_APAD + c*16;
        asm volatile("ldmatrix.sync.aligned.m8n8.x4.shared.b16 {%0,%1,%2,%3}, [%4];"
          : "=r"(fah[i].x), "=r"(fah[i].y), "=r"(fah[i].z), "=r"(fah[i].w) : "r"(ad));
        asm volatile("ldmatrix.sync.aligned.m8n8.x4.shared.b16 {%0,%1,%2,%3}, [%4];"
          : "=r"(fal[i].x), "=r"(fal[i].y), "=r"(fal[i].z), "=r"(fal[i].w) : "r"(ad + GT_OFFAL));
      }
      uint2 fwh[4], fwl[4];
      int kl = ks*16 + (lane & 15);
      #pragma unroll
      for (int j = 0; j < 4; j++) {
        uint32_t wd = cv + (uint32_t)kl*GT_WPAD + (uint32_t)(warpN*32 + j*8)*2;
        asm volatile("ldmatrix.sync.aligned.m8n8.x2.trans.shared.b16 {%0,%1}, [%2];"
          : "=r"(fwh[j].x), "=r"(fwh[j].y) : "r"(wd));
        asm volatile("ldmatrix.sync.aligned.m8n8.x2.trans.shared.b16 {%0,%1}, [%2];"
          : "=r"(fwl[j].x), "=r"(fwl[j].y) : "r"(wd + GT_CVLO));
      }
      #pragma unroll
      for (int i = 0; i < 2; i++)
        #pragma unroll
        for (int j = 0; j < 4; j++) MMA16816(acc[i][j], fah[i], fwh[j]);
      #pragma unroll
      for (int i = 0; i < 2; i++)
        #pragma unroll
        for (int j = 0; j < 4; j++) MMA16816(acc[i][j], fal[i], fwh[j]);
      #pragma unroll
      for (int i = 0; i < 2; i++)
        #pragma unroll
        for (int j = 0; j < 4; j++) MMA16816(acc[i][j], fah[i], fwl[j]);
    }
  }

  int g = lane >> 2, q = lane & 3;
  #pragma unroll
  for (int i = 0; i < 2; i++) {
    int m = m0 + warpM*32 + i*16 + g;
    #pragma unroll
    for (int j = 0; j < 4; j++) {
      int n = n0 + warpN*32 + j*8 + q*2;
      float b0 = bias[n], b1 = bias[n+1];
      float v00 = acc[i][j][0] + b0, v01 = acc[i][j][1] + b1;
      float v10 = acc[i][j][2] + b0, v11 = acc[i][j][3] + b1;
      if (mode == 1) {
        uint32_t ph0, pl0, ph1, pl1;
        split2(gelu_f(v00), gelu_f(v01), ph0, pl0);
        split2(gelu_f(v10), gelu_f(v11), ph1, pl1);
        *(uint32_t*)(Oh + (size_t)m*N + n)     = ph0;
        *(uint32_t*)(Ol + (size_t)m*N + n)     = pl0;
        *(uint32_t*)(Oh + (size_t)(m+8)*N + n) = ph1;
        *(uint32_t*)(Ol + (size_t)(m+8)*N + n) = pl1;
      } else {
        if (mode == 2) {
          float2 r0 = *(const float2*)(res + (size_t)m*N + n);
          float2 r1 = *(const float2*)(res + (size_t)(m+8)*N + n);
          v00 += r0.x; v01 += r0.y; v10 += r1.x; v11 += r1.y;
          *(uint32_t*)(Fh + (size_t)m*N + n)     = pack2h(v00, v01);
          *(uint32_t*)(Fh + (size_t)(m+8)*N + n) = pack2h(v10, v11);
        }
        *(float2*)(C + (size_t)m*N + n)     = make_float2(v00, v01);
        *(float2*)(C + (size_t)(m+8)*N + n) = make_float2(v10, v11);
      }
    }
  }
}

// ---------------- mass head --------------------------------------------------
__global__ void k_mass(const float* __restrict__ mw, const float* __restrict__ mb) {
  __shared__ float hs[32][E2c+1];
  __shared__ float ws[E2c*Hc];
  int r0 = blockIdx.x * 32;
  int tid = threadIdx.x;
  for (int idx = tid; idx < 32*E2c; idx += 256) {
    int r = idx / E2c, k = idx - (idx / E2c)*E2c;
    hs[r][k] = g_h[(r0 + r)*E2c + k];
  }
  for (int idx = tid; idx < E2c*Hc; idx += 256) ws[idx] = mw[idx];
  __syncthreads();
  int r = tid >> 3, hh = tid & 7;
  float acc = mb[hh];
  #pragma unroll 4
  for (int k = 0; k < E2c; k++) acc = fmaf(hs[r][k], ws[k*Hc + hh], acc);
  int row = r0 + r; int b = row >> 6, s = row & 63;
  g_mass[(b*Hc + hh)*Sc + s] = softplus_f(acc);
}

// ---------------- gravity attention core -------------------------------------
__global__ void k_attn() {
  int bh = blockIdx.x; int b = bh >> 3, hh = bh & 7;
  int i = threadIdx.x;
  __shared__ float qs[Sc][Dc+1];
  __shared__ float vs[Sc][Dc+1];
  __shared__ float ms[Sc];
  __shared__ float sq[Sc];
  const float* qbase = g_qk + (size_t)(b*Sc)*E2c + hh*Dc;
  const float* vbase = g_v  + (size_t)(b*Sc)*E2c + hh*Dc;
  float qi[Dc];
  float ssq = 0.f;
  #pragma unroll
  for (int d = 0; d < Dc; d++) {
    float q = qbase[i*E2c + d];
    qs[i][d] = q; qi[d] = q; ssq = fmaf(q, q, ssq);
    vs[i][d] = vbase[i*E2c + d];
  }
  sq[i] = ssq;
  ms[i] = g_mass[(b*Hc + hh)*Sc + i];
  __syncthreads();
  float mi = ms[i];
  float mmax = -INFINITY, l = 0.f;
  float acc[Dc];
  #pragma unroll
  for (int d = 0; d < Dc; d++) acc[d] = 0.f;
  for (int j = 0; j < Sc; j++) {
    float dot = 0.f;
    #pragma unroll
    for (int d = 0; d < Dc; d++) dot = fmaf(qi[d], qs[j][d], dot);
    float d2 = fmaxf(ssq + sq[j] - 2.f*dot, 0.f) + 1e-6f;
    float sc = mi * ms[j] / d2;
    float mn = fmaxf(mmax, sc);
    float scale = __expf(mmax - mn);
    float p = __expf(sc - mn);
    l = l*scale + p;
    #pragma unroll
    for (int d = 0; d < Dc; d++) acc[d] = fmaf(p, vs[j][d], acc[d]*scale);
    mmax = mn;
  }
  float inv = 1.f / l;
  float* obase = g_att + (size_t)(b*Sc + i)*E2c + hh*Dc;
  #pragma unroll
  for (int d = 0; d < Dc; d++) obase[d] = acc[d] * inv;
}

// ---------------- residual + LN + gelu (+ bf16 split fused) ------------------
__global__ void k_res_ln_gelu(const float* __restrict__ ls, const float* __restrict__ lo) {
  int row = blockIdx.x; int e = threadIdx.x;
  int idx = row*E2c + e;
  float v = g_h[idx] + g_att[idx];
  float s1 = v, s2 = v*v;
  blk_reduce2(s1, s2);
  float mu = s1 * (1.f/E2c);
  float var = s2 * (1.f/E2c) - mu*mu;
  float y = gelu_f((v - mu) * rsqrtf(var + 1e-5f) * ls[e] + lo[e]);
  g_h[idx] = y;
  __nv_bfloat16 hi = __float2bfloat16(y);
  g_Ah[idx] = hi;
  g_Al[idx] = __float2bfloat16(y - __bfloat162float(hi));
}

// ---------------- fc GEMM: fp16 single product, 2 CTAs/SM --------------------
// D[128, 48-slab] = fp16(A) @ fp16(W); grid=256, 8 warps (4m x 2n).
#define FC_BN 48
#define FC_BK 32
#define FC_IT (FLATc/FC_BK)     // 384
#define FC_ST 4
#define A_PAD 80                // 4 chunks + 1 pad
#define OFF_W32 10240           // A Fh tile 128x80
#define ST_SZ  16384            // 10240 + 6144 (32x192B fp32 W)
#define W_PAD 112               // 48 halves = 96B -> 7 chunks
#define CV_OFF (FC_ST*ST_SZ)    // 65536
#define FC_SMEM (CV_OFF + 32*W_PAD)   // 69120

__device__ __forceinline__ void fc_stage_load(uint32_t sb, int slot, int k0, int n0,
                                              const float* __restrict__ W, int tid) {
  uint32_t st = sb + slot*ST_SZ;
  // A: 128 rows x 4 chunks = 512 chunks, 2/thread
  #pragma unroll
  for (int t = 0; t < 2; t++) {
    int g = tid*2 + t;
    int m = g >> 2, c = g & 3;
    cp16(st + m*A_PAD + c*16, g_Fh + (size_t)m*FLATc + k0 + c*8);
  }
  // W fp32: 32 rows x 12 chunks = 384 chunks
  {
    int g = tid;
    if (g < 128) {
      int k0i = (g + 256) / 12, c = (g + 256) % 12;
      cp16(st + OFF_W32 + k0i*192 + c*16, W + (size_t)(k0 + k0i)*FLATc + n0 + c*4);
    }
    int k = g / 12, c = g % 12;
    if (g < 256) {
      cp16(st + OFF_W32 + k*192 + c*16, W + (size_t)(k0 + k)*FLATc + n0 + c*4);
    }
  }
}

__global__ void __launch_bounds__(256, 2) k_fc_mma(const float* __restrict__ W,
                                                   const float* __restrict__ bias) {
  extern __shared__ char smc[];
  uint32_t sb = smem_u32(smc);
  int tid = threadIdx.x, lane = tid & 31, wp = tid >> 5;
  int warpM = wp >> 1, warpN = wp & 1;
  int n0 = blockIdx.x * FC_BN;

  float acc[2][3][4];
  #pragma unroll
  for (int i = 0; i < 2; i++)
    #pragma unroll
    for (int j = 0; j < 3; j++)
      #pragma unroll
      for (int c = 0; c < 4; c++) acc[i][j][c] = 0.f;

  #pragma unroll
  for (int s = 0; s < FC_ST - 1; s++) {
    fc_stage_load(sb, s, s*FC_BK, n0, W, tid);
    asm volatile("cp.async.commit_group;" ::: "memory");
  }

  int arow = warpM*32 + (lane & 15);
  int ckrow = tid >> 3, cseg = tid & 7;

  for (int it = 0; it < FC_IT; it++) {
    asm volatile("cp.async.wait_group 2;" ::: "memory");
    __syncthreads();

    if (it + FC_ST - 1 < FC_IT) {
      fc_stage_load(sb, (it + FC_ST - 1) & 3, (it + FC_ST - 1)*FC_BK, n0, W, tid);
    }
    asm volatile("cp.async.commit_group;" ::: "memory");

    // convert fp32 W tile (stage it) -> fp16 CV buffer: 6 floats/thread
    {
      uint32_t src = sb + (it & 3)*ST_SZ + OFF_W32 + (uint32_t)ckrow*192 + cseg*24;
      uint32_t dh  = sb + CV_OFF + (uint32_t)ckrow*W_PAD + cseg*12;
      float2 f0, f1, f2;
      asm volatile("ld.shared.v2.f32 {%0,%1}, [%2];" : "=f"(f0.x), "=f"(f0.y) : "r"(src));
      asm volatile("ld.shared.v2.f32 {%0,%1}, [%2];" : "=f"(f1.x), "=f"(f1.y) : "r"(src + 8));
      asm volatile("ld.shared.v2.f32 {%0,%1}, [%2];" : "=f"(f2.x), "=f"(f2.y) : "r"(src + 16));
      uint32_t h0 = pack2h(f0.x, f0.y), h1 = pack2h(f1.x, f1.y), h2 = pack2h(f2.x, f2.y);
      asm volatile("st.shared.b32 [%0], %1;" :: "r"(dh),     "r"(h0));
      asm volatile("st.shared.b32 [%0], %1;" :: "r"(dh + 4), "r"(h1));
      asm volatile("st.shared.b32 [%0], %1;" :: "r"(dh + 8), "r"(h2));
    }
    __syncthreads();

    uint32_t st = sb + (it & 3)*ST_SZ;
    uint32_t cv = sb + CV_OFF;
    #pragma unroll
    for (int ks = 0; ks < 2; ks++) {
      uint4 fah[2];
      int c = ks*2 + (lane >> 4);
      #pragma unroll
      for (int i = 0; i < 2; i++) {
        uint32_t ad = st + (uint32_t)(arow + i*16)*A_PAD + c*16;
        asm volatile("ldmatrix.sync.aligned.m8n8.x4.shared.b16 {%0,%1,%2,%3}, [%4];"
          : "=r"(fah[i].x), "=r"(fah[i].y), "=r"(fah[i].z), "=r"(fah[i].w) : "r"(ad));
      }
      uint2 fwh[3];
      int kl = ks*16 + (lane & 15);
      #pragma unroll
      for (int j = 0; j < 3; j++) {
        uint32_t wd = cv + (uint32_t)kl*W_PAD + (uint32_t)(warpN*24 + j*8)*2;
        asm volatile("ldmatrix.sync.aligned.m8n8.x2.trans.shared.b16 {%0,%1}, [%2];"
          : "=r"(fwh[j].x), "=r"(fwh[j].y) : "r"(wd));
      }
      #pragma unroll
      for (int i = 0; i < 2; i++)
        #pragma unroll
        for (int j = 0; j < 3; j++) MMAH16816(acc[i][j], fah[i], fwh[j]);
    }
  }

  // epilogue: bias + gelu -> g_f
  int g = lane >> 2, q = lane & 3;
  #pragma unroll
  for (int i = 0; i < 2; i++) {
    int m = warpM*32 + i*16 + g;
    #pragma unroll
    for (int j = 0; j < 3; j++) {
      int n = n0 + warpN*24 + j*8 + q*2;
      float b0 = bias[n], b1 = bias[n+1];
      float2 r0, r1;
      r0.x = gelu_f(acc[i][j][0] + b0);
      r0.y = gelu_f(acc[i][j][1] + b1);
      r1.x = gelu_f(acc[i][j][2] + b0);
      r1.y = gelu_f(acc[i][j][3] + b1);
      *(float2*)(g_f + (size_t)m*FLATc + n)       = r0;
      *(float2*)(g_f + (size_t)(m + 8)*FLATc + n) = r1;
    }
  }
}

// ---------------- LN over FLAT -----------------------------------------------
__global__ void k_ln_flat(const float* __restrict__ ls, const float* __restrict__ lo) {
  int b = blockIdx.x; int t = threadIdx.x;
  float* frow = g_f + (size_t)b*FLATc;
  float s1 = 0.f, s2 = 0.f;
  for (int k = t; k < FLATc; k += 256) { float v = frow[k]; s1 += v; s2 += v*v; }
  blk_reduce2(s1, s2);
  float mu = s1 * (1.f/FLATc);
  float var = s2 * (1.f/FLATc) - mu*mu;
  float rs = rsqrtf(var + 1e-5f);
  for (int k = t; k < FLATc; k += 256) {
    float v = frow[k];
    frow[k] = (v - mu) * rs * ls[k] + lo[k];
  }
}

// ---------------- final out GEMM ---------------------------------------------
__global__ void k_out(const float* __restrict__ ow, const float* __restrict__ ob,
                      float* __restrict__ out) {
  int o = blockIdx.x, b = blockIdx.y;
  int t = threadIdx.x;
  const float* frow = g_f + (size_t)b*FLATc;
  float s1 = 0.f, s2 = 0.f;
  for (int k = t; k < FLATc; k += 256) s1 = fmaf(frow[k], ow[(size_t)k*HORc + o], s1);
  blk_reduce2(s1, s2);
  if (t == 0) out[b*HORc + o] = s1 + ob[o];
}

// ---------------- launch ------------------------------------------------------
extern "C" void kernel_launch(void* const* d_in, const int* in_sizes, int n_in,
                              void* d_out, int out_size) {
  const float* x      = (const float*)d_in[0];
  const float* proj_w = (const float*)d_in[1];
  const float* proj_b = (const float*)d_in[2];
  const float* ln0_s  = (const float*)d_in[3];
  const float* ln0_o  = (const float*)d_in[4];
  const float* conv_w = (const float*)d_in[5];
  const float* conv_b = (const float*)d_in[6];
  const float* ln1_s  = (const float*)d_in[7];
  const float* ln1_o  = (const float*)d_in[8];
  const float* qk_w   = (const float*)d_in[9];
  const float* qk_b   = (const float*)d_in[10];
  const float* mass_w = (const float*)d_in[11];
  const float* mass_b = (const float*)d_in[12];
  const float* v_w    = (const float*)d_in[13];
  const float* v_b    = (const float*)d_in[14];
  const float* norm_s = (const float*)d_in[15];
  const float* norm_o = (const float*)d_in[16];
  const float* mlp_w1 = (const float*)d_in[17];
  const float* mlp_b1 = (const float*)d_in[18];
  const float* mlp_w2 = (const float*)d_in[19];
  const float* mlp_b2 = (const float*)d_in[20];
  const float* fc_w   = (const float*)d_in[21];
  const float* fc_b   = (const float*)d_in[22];
  const float* ln2_s  = (const float*)d_in[23];
  const float* ln2_o  = (const float*)d_in[24];
  const float* out_w  = (const float*)d_in[25];
  const float* out_b  = (const float*)d_in[26];

  float *p_h, *p_qk, *p_v;
  __nv_bfloat16 *p_Ah, *p_Al, *p_Mh, *p_Ml;
  __half *p_Fh;
  cudaGetSymbolAddress((void**)&p_h,  g_h);
  cudaGetSymbolAddress((void**)&p_qk, g_qk);
  cudaGetSymbolAddress((void**)&p_v,  g_v);
  cudaGetSymbolAddress((void**)&p_Ah, g_Ah);
  cudaGetSymbolAddress((void**)&p_Al, g_Al);
  cudaGetSymbolAddress((void**)&p_Mh, g_Mh);
  cudaGetSymbolAddress((void**)&p_Ml, g_Ml);
  cudaGetSymbolAddress((void**)&p_Fh, g_Fh);

  cudaFuncSetAttribute(k_fc_mma, cudaFuncAttributeMaxDynamicSharedMemorySize, FC_SMEM);
  cudaFuncSetAttribute(k_gemm_tc, cudaFuncAttributeMaxDynamicSharedMemorySize, GT_SMEM);

  k_proj<<<ROWS, Ec>>>(x, proj_w, proj_b, ln0_s, ln0_o);
  k_conv<<<dim3(4, Bc), E2c>>>(conv_w);
  k_ln_gelu_conv<<<ROWS, E2c>>>(conv_b, ln1_s, ln1_o);

  for (int l = 0; l < Lc; l++) {
    k_gemm_tc<<<dim3(E2c/64, ROWS/128), 256, GT_SMEM>>>(
        p_Ah, p_Al, qk_w + (size_t)l*E2c*E2c, qk_b + l*E2c,
        nullptr, p_qk, nullptr, nullptr, nullptr, E2c, E2c, 0);
    k_gemm_tc<<<dim3(E2c/64, ROWS/128), 256, GT_SMEM>>>(
        p_Ah, p_Al, v_w + (size_t)l*E2c*E2c, v_b + l*E2c,
        nullptr, p_v, nullptr, nullptr, nullptr, E2c, E2c, 0);
    k_mass<<<ROWS/32, 256>>>(mass_w + (size_t)l*E2c*Hc, mass_b + l*Hc);
    k_attn<<<Bc*Hc, Sc>>>();
    k_res_ln_gelu<<<ROWS, E2c>>>(norm_s + l*E2c, norm_o + l*E2c);
  }

  // MLP: w1 (gelu -> bf16 pair), w2 (+residual, + fp16 for fc)
  k_gemm_tc<<<dim3(MLPH/64, ROWS/128), 256, GT_SMEM>>>(
      p_Ah, p_Al, mlp_w1, mlp_b1, nullptr, nullptr, p_Mh, p_Ml,
      nullptr, MLPH, E2c, 1);
  k_gemm_tc<<<dim3(E2c/64, ROWS/128), 256, GT_SMEM>>>(
      p_Mh, p_Ml, mlp_w2, mlp_b2, p_h, p_h, nullptr, nullptr,
      p_Fh, E2c, MLPH, 2);

  k_fc_mma<<<FLATc/FC_BN, 256, FC_SMEM>>>(fc_w, fc_b);
  k_ln_flat<<<Bc, 256>>>(ln2_s, ln2_o);
  k_out<<<dim3(HORc, Bc), 256>>>(out_w, out_b, (float*)d_out);
}